// round 10
// baseline (speedup 1.0000x reference)
#include <cuda_runtime.h>
#include <cuda_bf16.h>
#include <cstdint>
#include <math.h>

#define Bv   64
#define Sv   1024
#define Hv   1024
#define Ev   512
#define Vv   50257
#define D2H  2048
#define XK   3584   // 2H + E + H
#define G4H  4096
#define SPLITS 8

// ---------------- scratch (device globals; no runtime allocation) ----------
__device__ float g_hbias[Bv];
__device__ float g_partial_l[Bv * SPLITS];
__device__ float g_partial_acc[(size_t)Bv * SPLITS * D2H];   // 4 MB
__device__ float g_xfull[Bv * XK];
__device__ float g_gparts[4 * (size_t)Bv * G4H];              // 4 MB
__device__ float g_htf[Bv * Hv];                              // h_next, tf32-rounded

// =================== helpers (base PTX only, no sm_103a features) ==========
__device__ __forceinline__ uint32_t smem_u32(const void* p) {
    uint32_t a;
    asm("{ .reg .u64 tmp; cvta.to.shared.u64 tmp, %1; cvt.u32.u64 %0, tmp; }"
        : "=r"(a) : "l"(p));
    return a;
}
__device__ __forceinline__ uint32_t lds32(uint32_t addr) {
    uint32_t v;
    asm volatile("ld.shared.b32 %0, [%1];" : "=r"(v) : "r"(addr));
    return v;
}
__device__ __forceinline__ void sts_v2(uint32_t addr, uint32_t a, uint32_t b) {
    asm volatile("st.shared.v2.b32 [%0], {%1, %2};" :: "r"(addr), "r"(a), "r"(b));
}
__device__ __forceinline__ void sts32f(uint32_t addr, float v) {
    asm volatile("st.shared.f32 [%0], %1;" :: "r"(addr), "f"(v));
}
__device__ __forceinline__ float4 lds128f(uint32_t addr) {
    float4 v;
    asm volatile("ld.shared.v4.f32 {%0,%1,%2,%3}, [%4];"
        : "=f"(v.x), "=f"(v.y), "=f"(v.z), "=f"(v.w) : "r"(addr));
    return v;
}
__device__ __forceinline__ void cp16(uint32_t dst, const void* src) {
    asm volatile("cp.async.cg.shared.global [%0], [%1], 16;"
        :: "r"(dst), "l"(src) : "memory");
}
#define CP_COMMIT  asm volatile("cp.async.commit_group;" ::: "memory")
#define CP_WAIT(n) asm volatile("cp.async.wait_group %0;" :: "n"(n) : "memory")

__device__ __forceinline__ uint32_t sw128(uint32_t off) {
    return off ^ ((off >> 3) & 0x70);
}
// m16n8k16 bf16 MMA, f32 accum (base PTX, sm_80+)
__device__ __forceinline__ void hmma(float* c, const uint32_t* a, const uint32_t* b) {
    asm volatile(
        "mma.sync.aligned.m16n8k16.row.col.f32.bf16.bf16.f32 "
        "{%0,%1,%2,%3}, {%4,%5,%6,%7}, {%8,%9}, {%0,%1,%2,%3};"
        : "+f"(c[0]), "+f"(c[1]), "+f"(c[2]), "+f"(c[3])
        : "r"(a[0]), "r"(a[1]), "r"(a[2]), "r"(a[3]), "r"(b[0]), "r"(b[1]));
}
// m16n8k8 tf32 MMA, f32 accum (base PTX, sm_80+)
__device__ __forceinline__ void tmma(float* c, const uint32_t* a, const uint32_t* b) {
    asm volatile(
        "mma.sync.aligned.m16n8k8.row.col.f32.tf32.tf32.f32 "
        "{%0,%1,%2,%3}, {%4,%5,%6,%7}, {%8,%9}, {%0,%1,%2,%3};"
        : "+f"(c[0]), "+f"(c[1]), "+f"(c[2]), "+f"(c[3])
        : "r"(a[0]), "r"(a[1]), "r"(a[2]), "r"(a[3]), "r"(b[0]), "r"(b[1]));
}
__device__ __forceinline__ uint32_t to_tf32(uint32_t fbits) {
    uint32_t r;
    asm("cvt.rna.tf32.f32 %0, %1;" : "=r"(r) : "r"(fbits));
    return r;
}
// fp32x4 -> bf16 hi pair + lo (residual) pair
__device__ __forceinline__ void split4(float4 v, uint32_t& ha, uint32_t& hb,
                                       uint32_t& la, uint32_t& lb) {
    asm("cvt.rn.bf16x2.f32 %0, %1, %2;" : "=r"(ha) : "f"(v.y), "f"(v.x));
    asm("cvt.rn.bf16x2.f32 %0, %1, %2;" : "=r"(hb) : "f"(v.w), "f"(v.z));
    float rx = v.x - __uint_as_float(ha << 16);
    float ry = v.y - __uint_as_float(ha & 0xffff0000u);
    float rz = v.z - __uint_as_float(hb << 16);
    float rw = v.w - __uint_as_float(hb & 0xffff0000u);
    asm("cvt.rn.bf16x2.f32 %0, %1, %2;" : "=r"(la) : "f"(ry), "f"(rx));
    asm("cvt.rn.bf16x2.f32 %0, %1, %2;" : "=r"(lb) : "f"(rw), "f"(rz));
}

// gates kernel smem tile layout (bytes from aligned dynamic base)
#define T_A_HI 0
#define T_A_LO 16384
#define T_B_HI 32768
#define T_B_LO 40960
#define SMEM_DYN 49408
#define EPI_STRIDE 528          // 132 floats, 16B-aligned transpose stride

// vocab v5 smem: fp32 double-buffered A (2 x 32KB) + B (2 x 16KB)
#define V_A(c) ((uint32_t)(c) * 32768u)
#define V_B(c) (65536u + (uint32_t)(c) * 16384u)
#define SMEM_VOC 98432

// =============================================================
// Kernel 0a: hbias[b] = dot(hidden[b], We[2H:3H]) + be. grid (B).
// =============================================================
__global__ void __launch_bounds__(256) hbias_kernel(
    const float* __restrict__ hidden, const float* __restrict__ We,
    const float* __restrict__ be_p)
{
    const int b = blockIdx.x, t = threadIdx.x;
    const int lane = t & 31, wid = t >> 5;
    __shared__ float red[8];
    float4 hv = ((const float4*)hidden)[b * 256 + t];
    float4 wv = ((const float4*)We)[512 + t];
    float p = hv.x * wv.x + hv.y * wv.y + hv.z * wv.z + hv.w * wv.w;
#pragma unroll
    for (int o = 16; o > 0; o >>= 1) p += __shfl_xor_sync(0xffffffffu, p, o);
    if (lane == 0) red[wid] = p;
    __syncthreads();
    if (t == 0) {
        float s = be_p[0];
#pragma unroll
        for (int w = 0; w < 8; w++) s += red[w];
        g_hbias[b] = s;
    }
}

// =============================================================
// Kernel 0b: emb[x_tok[b]] -> xfull tail. grid (B).
// =============================================================
__global__ void __launch_bounds__(256) xemb_kernel(
    const float* __restrict__ emb, const int* __restrict__ x_tok)
{
    const int b = blockIdx.x, t = threadIdx.x;
    const int tok = x_tok[b];
    for (int j = t; j < Ev; j += 256)
        g_xfull[b * XK + D2H + j] = emb[(size_t)tok * Ev + j];
}

// =============================================================
// Kernel 0c: hidden -> xfull tail. grid (B).
// =============================================================
__global__ void __launch_bounds__(256) xhid_kernel(
    const float* __restrict__ hidden)
{
    const int b = blockIdx.x, t = threadIdx.x;
    for (int j = t; j < Hv; j += 256)
        g_xfull[b * XK + D2H + Ev + j] = hidden[b * Hv + j];
}

// =============================================================
// Kernel 1: attention. grid (SPLITS=8, B), 256 thr, 128 rows/CTA.
// 4-row tiles, register double-buffered loads, 1 sync/tile.
// Unnormalized softmax (relu energy >= 0, bounded; exp safe).
// =============================================================
__device__ __forceinline__ void attn_load(float4 ev[8], const float4* tbase, int t) {
#pragma unroll
    for (int r = 0; r < 4; r++) {
        ev[2 * r]     = tbase[r * 512 + t];
        ev[2 * r + 1] = tbase[r * 512 + 256 + t];
    }
}
__global__ void __launch_bounds__(256) attn_kernel(
    const float* __restrict__ enc, const float* __restrict__ We)
{
    const int b = blockIdx.y, sp = blockIdx.x, t = threadIdx.x;
    const int lane = t & 31, wid = t >> 5;
    __shared__ float red[2][8][4];

    const float4* We4 = (const float4*)We;
    const float4 w0 = We4[t];
    const float4 w1 = We4[256 + t];
    const float hb = g_hbias[b];

    float acc[8] = {0.f, 0.f, 0.f, 0.f, 0.f, 0.f, 0.f, 0.f};
    float lsum = 0.f;
    const float4* encb = (const float4*)enc + ((size_t)(b * Sv + sp * 128)) * 512;

    float4 evA[8], evB[8];
    attn_load(evA, encb, t);

#define ATTN_PROC(BUF, TILE_EXPR)                                              \
    {                                                                          \
        const int tile = (TILE_EXPR);                                          \
        const int par = tile & 1;                                              \
        float d[4];                                                            \
        _Pragma("unroll")                                                      \
        for (int r = 0; r < 4; r++) {                                          \
            d[r] = BUF[2*r].x * w0.x + BUF[2*r].y * w0.y                       \
                 + BUF[2*r].z * w0.z + BUF[2*r].w * w0.w                       \
                 + BUF[2*r+1].x * w1.x + BUF[2*r+1].y * w1.y                   \
                 + BUF[2*r+1].z * w1.z + BUF[2*r+1].w * w1.w;                  \
            _Pragma("unroll")                                                  \
            for (int o = 16; o > 0; o >>= 1)                                   \
                d[r] += __shfl_xor_sync(0xffffffffu, d[r], o);                 \
        }                                                                      \
        if (lane == 0) {                                                       \
            _Pragma("unroll")                                                  \
            for (int r = 0; r < 4; r++) red[par][wid][r] = d[r];               \
        }                                                                      \
        __syncthreads();                                                       \
        _Pragma("unroll")                                                      \
        for (int r = 0; r < 4; r++) {                                          \
            float s = hb;                                                      \
            _Pragma("unroll")                                                  \
            for (int w2 = 0; w2 < 8; w2++) s += red[par][w2][r];               \
            s = fmaxf(s, 0.f);                                                 \
            float wgt = __expf(s);                                             \
            lsum += wgt;                                                       \
            acc[0] += wgt * BUF[2*r].x;   acc[1] += wgt * BUF[2*r].y;          \
            acc[2] += wgt * BUF[2*r].z;   acc[3] += wgt * BUF[2*r].w;          \
            acc[4] += wgt * BUF[2*r+1].x; acc[5] += wgt * BUF[2*r+1].y;        \
            acc[6] += wgt * BUF[2*r+1].z; acc[7] += wgt * BUF[2*r+1].w;        \
        }                                                                      \
    }

    for (int tp = 0; tp < 16; tp++) {
        attn_load(evB, encb + (size_t)(2 * tp + 1) * 4 * 512, t);
        ATTN_PROC(evA, 2 * tp);
        if (tp < 15)
            attn_load(evA, encb + (size_t)(2 * tp + 2) * 4 * 512, t);
        ATTN_PROC(evB, 2 * tp + 1);
    }
#undef ATTN_PROC

    float4* pacc = (float4*)(g_partial_acc + ((size_t)(b * SPLITS + sp)) * D2H);
    pacc[t]       = make_float4(acc[0], acc[1], acc[2], acc[3]);
    pacc[256 + t] = make_float4(acc[4], acc[5], acc[6], acc[7]);
    if (t == 0) g_partial_l[b * SPLITS + sp] = lsum;
}

// =============================================================
// Kernel 2: combine partials -> c_i (head of x_full). grid (8, B).
// =============================================================
__global__ void __launch_bounds__(256) combine_kernel()
{
    const int q = blockIdx.x, b = blockIdx.y, t = threadIdx.x;
    float s = 0.f;
#pragma unroll
    for (int i = 0; i < SPLITS; i++) s += g_partial_l[b * SPLITS + i];
    const float inv = 1.f / s;
    const int c = q * 256 + t;
    float a = 0.f;
#pragma unroll
    for (int i = 0; i < SPLITS; i++)
        a += g_partial_acc[((size_t)(b * SPLITS + i)) * D2H + c];
    g_xfull[b * XK + c] = a * inv;
}

// ============= bf16 MMA fragment loaders (gates kernel) ===============
__device__ __forceinline__ void frag_a(uint32_t tile, int w, int g, int tg,
                                       int ks, uint32_t a[4]) {
    uint32_t r0 = (uint32_t)(16 * w + g);
    uint32_t k0 = (uint32_t)((16 * ks + 2 * tg) * 2);
    a[0] = lds32(tile + sw128(r0 * 128 + k0));
    a[1] = lds32(tile + sw128((r0 + 8) * 128 + k0));
    a[2] = lds32(tile + sw128(r0 * 128 + k0 + 16));
    a[3] = lds32(tile + sw128((r0 + 8) * 128 + k0 + 16));
}
__device__ __forceinline__ void frag_b(uint32_t tile, int j, int g, int tg,
                                       int ks, uint32_t bfr[2]) {
    uint32_t n = (uint32_t)(8 * j + g);
    uint32_t k0 = (uint32_t)((16 * ks + 2 * tg) * 2);
    bfr[0] = lds32(tile + sw128(n * 128 + k0));
    bfr[1] = lds32(tile + sw128(n * 128 + k0 + 16));
}

// =============================================================
// Kernel 3: gates GEMM (HMMA split-bf16). grid (32 gate-tiles, 4 K-splits).
// =============================================================
__global__ void __launch_bounds__(256) gates_mma(
    const float* __restrict__ W_ih, const float* __restrict__ W_hh)
{
    extern __shared__ char dsm[];
    const uint32_t sb = (smem_u32(dsm) + 127u) & ~127u;
    const int t = threadIdx.x, w = t >> 5, lane = t & 31;
    const int g = lane >> 2, tg = lane & 3;
    const int gbase = blockIdx.x * 128;
    const int ks_split = blockIdx.y;

    float acc[8][4] = {};
    float4 aP[8], bP[4];

    {
        const int kg = ks_split * 896;
        const bool ih = (kg < 2560);
#pragma unroll
        for (int i = 0; i < 8; i++) {
            int e = i * 256 + t, row = e >> 4, c4 = e & 15;
            int og = gbase + row;
            aP[i] = ih ? *(const float4*)(W_ih + (size_t)og * 2560 + kg + c4 * 4)
                       : *(const float4*)(W_hh + (size_t)og * 1024 + (kg - 2560) + c4 * 4);
        }
#pragma unroll
        for (int i = 0; i < 4; i++) {
            int e = i * 256 + t, row = e >> 4, c4 = e & 15;
            bP[i] = *(const float4*)(g_xfull + (size_t)row * XK + kg + c4 * 4);
        }
    }

    for (int ch = 0; ch < 14; ch++) {
        __syncthreads();
#pragma unroll
        for (int i = 0; i < 8; i++) {
            int e = i * 256 + t, row = e >> 4, c4 = e & 15;
            uint32_t ha, hb2, la, lb; split4(aP[i], ha, hb2, la, lb);
            uint32_t off = sw128((uint32_t)(row * 128 + c4 * 8));
            sts_v2(sb + T_A_HI + off, ha, hb2);
            sts_v2(sb + T_A_LO + off, la, lb);
        }
#pragma unroll
        for (int i = 0; i < 4; i++) {
            int e = i * 256 + t, row = e >> 4, c4 = e & 15;
            uint32_t ha, hb2, la, lb; split4(bP[i], ha, hb2, la, lb);
            uint32_t off = sw128((uint32_t)(row * 128 + c4 * 8));
            sts_v2(sb + T_B_HI + off, ha, hb2);
            sts_v2(sb + T_B_LO + off, la, lb);
        }
        __syncthreads();
        if (ch + 1 < 14) {
            const int kg = ks_split * 896 + (ch + 1) * 64;
            const bool ih = (kg < 2560);
#pragma unroll
            for (int i = 0; i < 8; i++) {
                int e = i * 256 + t, row = e >> 4, c4 = e & 15;
                int og = gbase + row;
                aP[i] = ih ? *(const float4*)(W_ih + (size_t)og * 2560 + kg + c4 * 4)
                           : *(const float4*)(W_hh + (size_t)og * 1024 + (kg - 2560) + c4 * 4);
            }
#pragma unroll
            for (int i = 0; i < 4; i++) {
                int e = i * 256 + t, row = e >> 4, c4 = e & 15;
                bP[i] = *(const float4*)(g_xfull + (size_t)row * XK + kg + c4 * 4);
            }
        }
#pragma unroll
        for (int ks = 0; ks < 4; ks++) {
            uint32_t ahi[4], alo[4];
            frag_a(sb + T_A_HI, w, g, tg, ks, ahi);
            frag_a(sb + T_A_LO, w, g, tg, ks, alo);
#pragma unroll
            for (int jh = 0; jh < 2; jh++) {
                uint32_t bh[4][2], bl[4][2];
#pragma unroll
                for (int jj = 0; jj < 4; jj++) {
                    frag_b(sb + T_B_HI, jh * 4 + jj, g, tg, ks, bh[jj]);
                    frag_b(sb + T_B_LO, jh * 4 + jj, g, tg, ks, bl[jj]);
                }
#pragma unroll
                for (int jj = 0; jj < 4; jj++) hmma(acc[jh * 4 + jj], ahi, bh[jj]);
#pragma unroll
                for (int jj = 0; jj < 4; jj++) hmma(acc[jh * 4 + jj], alo, bh[jj]);
#pragma unroll
                for (int jj = 0; jj < 4; jj++) hmma(acc[jh * 4 + jj], ahi, bl[jj]);
            }
        }
    }
    __syncthreads();
#pragma unroll
    for (int j = 0; j < 8; j++) {
#pragma unroll
        for (int k = 0; k < 4; k++) {
            int bb = 8 * j + 2 * tg + (k & 1);
            int vl = 16 * w + g + ((k >> 1) ? 8 : 0);
            sts32f(sb + (uint32_t)(bb * EPI_STRIDE + vl * 4), acc[j][k]);
        }
    }
    __syncthreads();
    float* gp = g_gparts + (size_t)ks_split * (Bv * G4H);
#pragma unroll
    for (int i = 0; i < 8; i++) {
        int e = i * 256 + t, bb = e >> 5, c4 = e & 31;
        float4 v = lds128f(sb + (uint32_t)(bb * EPI_STRIDE + c4 * 16));
        *(float4*)(gp + (size_t)bb * G4H + gbase + c4 * 4) = v;
    }
}

// =============================================================
// Kernel 4: split-K sum + biases + LSTM pointwise; also emits
// h_next rounded to tf32 for the vocab GEMM. grid (4, B).
// =============================================================
__global__ void __launch_bounds__(256) lstm_kernel(
    const float* __restrict__ cell, const float* __restrict__ b_ih,
    const float* __restrict__ b_hh, float* __restrict__ out)
{
    const int b = blockIdx.y, h = blockIdx.x * 256 + threadIdx.x;
    float* h_out = out + (size_t)Bv * Vv;
    float* c_out = h_out + Bv * Hv;
    const int base = b * G4H;
    float gi = 0.f, gf = 0.f, gg = 0.f, go = 0.f;
#pragma unroll
    for (int ksv = 0; ksv < 4; ksv++) {
        const float* gp = g_gparts + (size_t)ksv * (Bv * G4H);
        gi += gp[base + h];
        gf += gp[base + 1024 + h];
        gg += gp[base + 2048 + h];
        go += gp[base + 3072 + h];
    }
    gi += b_ih[h]        + b_hh[h];
    gf += b_ih[1024 + h] + b_hh[1024 + h];
    gg += b_ih[2048 + h] + b_hh[2048 + h];
    go += b_ih[3072 + h] + b_hh[3072 + h];
    float si = 1.f / (1.f + expf(-gi));
    float sf = 1.f / (1.f + expf(-gf));
    float so = 1.f / (1.f + expf(-go));
    float c  = sf * cell[b * Hv + h] + si * tanhf(gg);
    float hn = so * tanhf(c);
    c_out[b * Hv + h] = c;
    h_out[b * Hv + h] = hn;
    g_htf[b * Hv + h] = __uint_as_float(to_tf32(__float_as_uint(hn)));
}

// =============================================================
// Kernel 5: vocab GEMM v5 — single-pass TF32. grid (393), 256 thr.
// A (Wf fp32) and B (g_htf, pre-rounded) stream via cp.async into
// swizzled fp32 tiles (double-buffered). 64 tf32-HMMA per chunk
// (vs 96 bf16); A cvt.rna at frag load; B needs no cvt.
// =============================================================
__global__ void __launch_bounds__(256) vocab_mma(
    const float* __restrict__ Wf, const float* __restrict__ bf,
    float* __restrict__ pred)
{
    extern __shared__ char dsm[];
    const uint32_t sb = (smem_u32(dsm) + 127u) & ~127u;
    const int t = threadIdx.x, w = t >> 5, lane = t & 31;
    const int g = lane >> 2, tg = lane & 3;
    const int vbase = blockIdx.x * 128;

    float acc[8][4] = {};

    // chunk 0: cp.async A + B into buf 0
    {
#pragma unroll
        for (int i = 0; i < 8; i++) {
            int e = i * 256 + t, row = e >> 4, seg = e & 15;
            int vg = vbase + row;
            if (vg < Vv)
                cp16(sb + V_A(0) + sw128((uint32_t)(row * 256 + seg * 16)),
                     Wf + (size_t)vg * Hv + seg * 4);
        }
#pragma unroll
        for (int i = 0; i < 4; i++) {
            int e = i * 256 + t, n = e >> 4, seg = e & 15;
            cp16(sb + V_B(0) + sw128((uint32_t)(n * 256 + seg * 16)),
                 g_htf + (size_t)n * Hv + seg * 4);
        }
        CP_COMMIT;
    }
    CP_WAIT(0);
    __syncthreads();

    for (int ch = 0; ch < 16; ch++) {
        const uint32_t cur = (uint32_t)(ch & 1);
        const uint32_t aT = sb + V_A(cur);
        const uint32_t bT = sb + V_B(cur);
        const bool more = (ch + 1 < 16);

        // cp.async next chunk into the other buffers
        if (more) {
            const uint32_t nxt = cur ^ 1u;
            const int kb = (ch + 1) * 64;
#pragma unroll
            for (int i = 0; i < 8; i++) {
                int e = i * 256 + t, row = e >> 4, seg = e & 15;
                int vg = vbase + row;
                if (vg < Vv)
                    cp16(sb + V_A(nxt) + sw128((uint32_t)(row * 256 + seg * 16)),
                         Wf + (size_t)vg * Hv + kb + seg * 4);
            }
#pragma unroll
            for (int i = 0; i < 4; i++) {
                int e = i * 256 + t, n = e >> 4, seg = e & 15;
                cp16(sb + V_B(nxt) + sw128((uint32_t)(n * 256 + seg * 16)),
                     g_htf + (size_t)n * Hv + kb + seg * 4);
            }
            CP_COMMIT;
        }

        // 8 k8-steps of tf32 MMA on cur buffers
        const uint32_t r0 = (uint32_t)(16 * w + g);
#pragma unroll
        for (int k8 = 0; k8 < 8; k8++) {
            const uint32_t kc0 = (uint32_t)((k8 * 8 + tg) * 4);
            uint32_t a[4];
            a[0] = to_tf32(lds32(aT + sw128(r0 * 256 + kc0)));
            a[1] = to_tf32(lds32(aT + sw128((r0 + 8) * 256 + kc0)));
            a[2] = to_tf32(lds32(aT + sw128(r0 * 256 + kc0 + 16)));
            a[3] = to_tf32(lds32(aT + sw128((r0 + 8) * 256 + kc0 + 16)));
#pragma unroll
            for (int j = 0; j < 8; j++) {
                uint32_t n = (uint32_t)(8 * j + g);
                uint32_t b2[2];
                b2[0] = lds32(bT + sw128(n * 256 + kc0));       // pre-rounded tf32
                b2[1] = lds32(bT + sw128(n * 256 + kc0 + 16));
                tmma(acc[j], a, b2);
            }
        }
        CP_WAIT(0);
        __syncthreads();
    }

    // epilogue: transpose via smem (reuses tile space), add bias, STG
    // (pred row stride Vv=50257 not 16B-aligned -> scalar stores)
#pragma unroll
    for (int j = 0; j < 8; j++) {
#pragma unroll
        for (int k = 0; k < 4; k++) {
            int bb = 8 * j + 2 * tg + (k & 1);
            int vl = 16 * w + g + ((k >> 1) ? 8 : 0);
            sts32f(sb + (uint32_t)(bb * EPI_STRIDE + vl * 4), acc[j][k]);
        }
    }
    __syncthreads();
#pragma unroll
    for (int i = 0; i < 8; i++) {
        int e = i * 256 + t, bb = e >> 5, c4 = e & 31;
        float4 v = lds128f(sb + (uint32_t)(bb * EPI_STRIDE + c4 * 16));
        int vg = vbase + c4 * 4;
        float* prow = pred + (size_t)bb * Vv;
        float vv[4] = {v.x, v.y, v.z, v.w};
#pragma unroll
        for (int d = 0; d < 4; d++)
            if (vg + d < Vv) prow[vg + d] = vv[d] + bf[vg + d];
    }
}

// =============================================================
extern "C" void kernel_launch(void* const* d_in, const int* in_sizes, int n_in,
                              void* d_out, int out_size)
{
    const float* enc    = (const float*)d_in[0];
    const int*   x_tok  = (const int*)  d_in[1];
    const float* hidden = (const float*)d_in[2];
    const float* cell   = (const float*)d_in[3];
    const float* emb    = (const float*)d_in[4];
    const float* We     = (const float*)d_in[5];
    const float* be     = (const float*)d_in[6];
    const float* W_ih   = (const float*)d_in[7];
    const float* W_hh   = (const float*)d_in[8];
    const float* b_ih   = (const float*)d_in[9];
    const float* b_hh   = (const float*)d_in[10];
    const float* Wf     = (const float*)d_in[11];
    const float* bf     = (const float*)d_in[12];

    float* out   = (float*)d_out;
    float* pred  = out;                          // [B, V]

    cudaFuncSetAttribute(gates_mma, cudaFuncAttributeMaxDynamicSharedMemorySize, SMEM_DYN);
    cudaFuncSetAttribute(vocab_mma, cudaFuncAttributeMaxDynamicSharedMemorySize, SMEM_VOC);

    hbias_kernel  <<<Bv, 256>>>(hidden, We, be);
    xemb_kernel   <<<Bv, 256>>>(emb, x_tok);
    xhid_kernel   <<<Bv, 256>>>(hidden);
    attn_kernel   <<<dim3(SPLITS, Bv), 256>>>(enc, We);
    combine_kernel<<<dim3(8, Bv), 256>>>();
    gates_mma     <<<dim3(32, 4), 256, SMEM_DYN>>>(W_ih, W_hh);
    lstm_kernel   <<<dim3(4, Bv), 256>>>(cell, b_ih, b_hh, out);
    vocab_mma     <<<(Vv + 127) / 128, 256, SMEM_VOC>>>(Wf, bf, pred);
}

// round 11
// speedup vs baseline: 1.2126x; 1.2126x over previous
#include <cuda_runtime.h>
#include <cuda_bf16.h>
#include <cuda_fp16.h>
#include <cstdint>
#include <math.h>

#define Bv   64
#define Sv   1024
#define Hv   1024
#define Ev   512
#define Vv   50257
#define D2H  2048
#define XK   3584   // 2H + E + H
#define G4H  4096
#define SPLITS 8

// ---------------- scratch (device globals; no runtime allocation) ----------
__device__ float g_hbias[Bv];
__device__ float g_partial_l[Bv * SPLITS];
__device__ float g_partial_acc[(size_t)Bv * SPLITS * D2H];   // 4 MB
__device__ float g_xfull[Bv * XK];
__device__ float g_gparts[4 * (size_t)Bv * G4H];              // 4 MB
__device__ __half g_hf16[Bv * Hv];                            // h_next fp16

// =================== helpers (base PTX only, no sm_103a features) ==========
__device__ __forceinline__ uint32_t smem_u32(const void* p) {
    uint32_t a;
    asm("{ .reg .u64 tmp; cvta.to.shared.u64 tmp, %1; cvt.u32.u64 %0, tmp; }"
        : "=r"(a) : "l"(p));
    return a;
}
__device__ __forceinline__ uint32_t lds32(uint32_t addr) {
    uint32_t v;
    asm volatile("ld.shared.b32 %0, [%1];" : "=r"(v) : "r"(addr));
    return v;
}
__device__ __forceinline__ void sts_v2(uint32_t addr, uint32_t a, uint32_t b) {
    asm volatile("st.shared.v2.b32 [%0], {%1, %2};" :: "r"(addr), "r"(a), "r"(b));
}
__device__ __forceinline__ void sts32f(uint32_t addr, float v) {
    asm volatile("st.shared.f32 [%0], %1;" :: "r"(addr), "f"(v));
}
__device__ __forceinline__ float4 lds128f(uint32_t addr) {
    float4 v;
    asm volatile("ld.shared.v4.f32 {%0,%1,%2,%3}, [%4];"
        : "=f"(v.x), "=f"(v.y), "=f"(v.z), "=f"(v.w) : "r"(addr));
    return v;
}
__device__ __forceinline__ void cp16(uint32_t dst, const void* src) {
    asm volatile("cp.async.cg.shared.global [%0], [%1], 16;"
        :: "r"(dst), "l"(src) : "memory");
}
#define CP_COMMIT  asm volatile("cp.async.commit_group;" ::: "memory")
#define CP_WAIT(n) asm volatile("cp.async.wait_group %0;" :: "n"(n) : "memory")

__device__ __forceinline__ uint32_t sw128(uint32_t off) {
    return off ^ ((off >> 3) & 0x70);
}
// m16n8k16 bf16 MMA, f32 accum (base PTX, sm_80+)
__device__ __forceinline__ void hmma(float* c, const uint32_t* a, const uint32_t* b) {
    asm volatile(
        "mma.sync.aligned.m16n8k16.row.col.f32.bf16.bf16.f32 "
        "{%0,%1,%2,%3}, {%4,%5,%6,%7}, {%8,%9}, {%0,%1,%2,%3};"
        : "+f"(c[0]), "+f"(c[1]), "+f"(c[2]), "+f"(c[3])
        : "r"(a[0]), "r"(a[1]), "r"(a[2]), "r"(a[3]), "r"(b[0]), "r"(b[1]));
}
// m16n8k16 fp16 MMA, f32 accum (base PTX, sm_80+)
__device__ __forceinline__ void fmma(float* c, const uint32_t* a, const uint32_t* b) {
    asm volatile(
        "mma.sync.aligned.m16n8k16.row.col.f32.f16.f16.f32 "
        "{%0,%1,%2,%3}, {%4,%5,%6,%7}, {%8,%9}, {%0,%1,%2,%3};"
        : "+f"(c[0]), "+f"(c[1]), "+f"(c[2]), "+f"(c[3])
        : "r"(a[0]), "r"(a[1]), "r"(a[2]), "r"(a[3]), "r"(b[0]), "r"(b[1]));
}
// fp32x4 -> bf16 hi pair + lo (residual) pair (gates kernel)
__device__ __forceinline__ void split4(float4 v, uint32_t& ha, uint32_t& hb,
                                       uint32_t& la, uint32_t& lb) {
    asm("cvt.rn.bf16x2.f32 %0, %1, %2;" : "=r"(ha) : "f"(v.y), "f"(v.x));
    asm("cvt.rn.bf16x2.f32 %0, %1, %2;" : "=r"(hb) : "f"(v.w), "f"(v.z));
    float rx = v.x - __uint_as_float(ha << 16);
    float ry = v.y - __uint_as_float(ha & 0xffff0000u);
    float rz = v.z - __uint_as_float(hb << 16);
    float rw = v.w - __uint_as_float(hb & 0xffff0000u);
    asm("cvt.rn.bf16x2.f32 %0, %1, %2;" : "=r"(la) : "f"(ry), "f"(rx));
    asm("cvt.rn.bf16x2.f32 %0, %1, %2;" : "=r"(lb) : "f"(rw), "f"(rz));
}
// fp32x4 -> fp16x2 pair (vocab kernel)
__device__ __forceinline__ void cvt_h4(float4 v, uint32_t& ha, uint32_t& hb) {
    asm("cvt.rn.f16x2.f32 %0, %1, %2;" : "=r"(ha) : "f"(v.y), "f"(v.x));
    asm("cvt.rn.f16x2.f32 %0, %1, %2;" : "=r"(hb) : "f"(v.w), "f"(v.z));
}

// gates kernel smem tile layout (bytes from aligned dynamic base)
#define T_A_HI 0
#define T_A_LO 16384
#define T_B_HI 32768
#define T_B_LO 40960
#define SMEM_DYN 49408
#define EPI_STRIDE 528          // 132 floats, 16B-aligned transpose stride

// vocab v6 smem: fp16 double-buffered A (2 x 16KB) + B (2 x 8KB)
#define V_A(c) ((uint32_t)(c) * 16384u)
#define V_B(c) (32768u + (uint32_t)(c) * 8192u)
#define SMEM_VOC 49408

// =============================================================
// Kernel 0a: hbias[b] = dot(hidden[b], We[2H:3H]) + be. grid (B).
// =============================================================
__global__ void __launch_bounds__(256) hbias_kernel(
    const float* __restrict__ hidden, const float* __restrict__ We,
    const float* __restrict__ be_p)
{
    const int b = blockIdx.x, t = threadIdx.x;
    const int lane = t & 31, wid = t >> 5;
    __shared__ float red[8];
    float4 hv = ((const float4*)hidden)[b * 256 + t];
    float4 wv = ((const float4*)We)[512 + t];
    float p = hv.x * wv.x + hv.y * wv.y + hv.z * wv.z + hv.w * wv.w;
#pragma unroll
    for (int o = 16; o > 0; o >>= 1) p += __shfl_xor_sync(0xffffffffu, p, o);
    if (lane == 0) red[wid] = p;
    __syncthreads();
    if (t == 0) {
        float s = be_p[0];
#pragma unroll
        for (int w = 0; w < 8; w++) s += red[w];
        g_hbias[b] = s;
    }
}

// =============================================================
// Kernel 0b: emb[x_tok[b]] -> xfull tail. grid (B).
// =============================================================
__global__ void __launch_bounds__(256) xemb_kernel(
    const float* __restrict__ emb, const int* __restrict__ x_tok)
{
    const int b = blockIdx.x, t = threadIdx.x;
    const int tok = x_tok[b];
    for (int j = t; j < Ev; j += 256)
        g_xfull[b * XK + D2H + j] = emb[(size_t)tok * Ev + j];
}

// =============================================================
// Kernel 0c: hidden -> xfull tail. grid (B).
// =============================================================
__global__ void __launch_bounds__(256) xhid_kernel(
    const float* __restrict__ hidden)
{
    const int b = blockIdx.x, t = threadIdx.x;
    for (int j = t; j < Hv; j += 256)
        g_xfull[b * XK + D2H + Ev + j] = hidden[b * Hv + j];
}

// =============================================================
// Kernel 1: attention. grid (SPLITS=8, B), 256 thr, 128 rows/CTA.
// 4-row tiles, register double-buffered loads, 1 sync/tile.
// Unnormalized softmax (relu energy >= 0, bounded; exp safe).
// =============================================================
__device__ __forceinline__ void attn_load(float4 ev[8], const float4* tbase, int t) {
#pragma unroll
    for (int r = 0; r < 4; r++) {
        ev[2 * r]     = tbase[r * 512 + t];
        ev[2 * r + 1] = tbase[r * 512 + 256 + t];
    }
}
__global__ void __launch_bounds__(256) attn_kernel(
    const float* __restrict__ enc, const float* __restrict__ We)
{
    const int b = blockIdx.y, sp = blockIdx.x, t = threadIdx.x;
    const int lane = t & 31, wid = t >> 5;
    __shared__ float red[2][8][4];

    const float4* We4 = (const float4*)We;
    const float4 w0 = We4[t];
    const float4 w1 = We4[256 + t];
    const float hb = g_hbias[b];

    float acc[8] = {0.f, 0.f, 0.f, 0.f, 0.f, 0.f, 0.f, 0.f};
    float lsum = 0.f;
    const float4* encb = (const float4*)enc + ((size_t)(b * Sv + sp * 128)) * 512;

    float4 evA[8], evB[8];
    attn_load(evA, encb, t);

#define ATTN_PROC(BUF, TILE_EXPR)                                              \
    {                                                                          \
        const int tile = (TILE_EXPR);                                          \
        const int par = tile & 1;                                              \
        float d[4];                                                            \
        _Pragma("unroll")                                                      \
        for (int r = 0; r < 4; r++) {                                          \
            d[r] = BUF[2*r].x * w0.x + BUF[2*r].y * w0.y                       \
                 + BUF[2*r].z * w0.z + BUF[2*r].w * w0.w                       \
                 + BUF[2*r+1].x * w1.x + BUF[2*r+1].y * w1.y                   \
                 + BUF[2*r+1].z * w1.z + BUF[2*r+1].w * w1.w;                  \
            _Pragma("unroll")                                                  \
            for (int o = 16; o > 0; o >>= 1)                                   \
                d[r] += __shfl_xor_sync(0xffffffffu, d[r], o);                 \
        }                                                                      \
        if (lane == 0) {                                                       \
            _Pragma("unroll")                                                  \
            for (int r = 0; r < 4; r++) red[par][wid][r] = d[r];               \
        }                                                                      \
        __syncthreads();                                                       \
        _Pragma("unroll")                                                      \
        for (int r = 0; r < 4; r++) {                                          \
            float s = hb;                                                      \
            _Pragma("unroll")                                                  \
            for (int w2 = 0; w2 < 8; w2++) s += red[par][w2][r];               \
            s = fmaxf(s, 0.f);                                                 \
            float wgt = __expf(s);                                             \
            lsum += wgt;                                                       \
            acc[0] += wgt * BUF[2*r].x;   acc[1] += wgt * BUF[2*r].y;          \
            acc[2] += wgt * BUF[2*r].z;   acc[3] += wgt * BUF[2*r].w;          \
            acc[4] += wgt * BUF[2*r+1].x; acc[5] += wgt * BUF[2*r+1].y;        \
            acc[6] += wgt * BUF[2*r+1].z; acc[7] += wgt * BUF[2*r+1].w;        \
        }                                                                      \
    }

    for (int tp = 0; tp < 16; tp++) {
        attn_load(evB, encb + (size_t)(2 * tp + 1) * 4 * 512, t);
        ATTN_PROC(evA, 2 * tp);
        if (tp < 15)
            attn_load(evA, encb + (size_t)(2 * tp + 2) * 4 * 512, t);
        ATTN_PROC(evB, 2 * tp + 1);
    }
#undef ATTN_PROC

    float4* pacc = (float4*)(g_partial_acc + ((size_t)(b * SPLITS + sp)) * D2H);
    pacc[t]       = make_float4(acc[0], acc[1], acc[2], acc[3]);
    pacc[256 + t] = make_float4(acc[4], acc[5], acc[6], acc[7]);
    if (t == 0) g_partial_l[b * SPLITS + sp] = lsum;
}

// =============================================================
// Kernel 2: combine partials -> c_i (head of x_full). grid (8, B).
// =============================================================
__global__ void __launch_bounds__(256) combine_kernel()
{
    const int q = blockIdx.x, b = blockIdx.y, t = threadIdx.x;
    float s = 0.f;
#pragma unroll
    for (int i = 0; i < SPLITS; i++) s += g_partial_l[b * SPLITS + i];
    const float inv = 1.f / s;
    const int c = q * 256 + t;
    float a = 0.f;
#pragma unroll
    for (int i = 0; i < SPLITS; i++)
        a += g_partial_acc[((size_t)(b * SPLITS + i)) * D2H + c];
    g_xfull[b * XK + c] = a * inv;
}

// ============= MMA fragment loaders (shared addressing) ===============
__device__ __forceinline__ void frag_a(uint32_t tile, int w, int g, int tg,
                                       int ks, uint32_t a[4]) {
    uint32_t r0 = (uint32_t)(16 * w + g);
    uint32_t k0 = (uint32_t)((16 * ks + 2 * tg) * 2);
    a[0] = lds32(tile + sw128(r0 * 128 + k0));
    a[1] = lds32(tile + sw128((r0 + 8) * 128 + k0));
    a[2] = lds32(tile + sw128(r0 * 128 + k0 + 16));
    a[3] = lds32(tile + sw128((r0 + 8) * 128 + k0 + 16));
}
__device__ __forceinline__ void frag_b(uint32_t tile, int j, int g, int tg,
                                       int ks, uint32_t bfr[2]) {
    uint32_t n = (uint32_t)(8 * j + g);
    uint32_t k0 = (uint32_t)((16 * ks + 2 * tg) * 2);
    bfr[0] = lds32(tile + sw128(n * 128 + k0));
    bfr[1] = lds32(tile + sw128(n * 128 + k0 + 16));
}

// =============================================================
// Kernel 3: gates GEMM (HMMA split-bf16). grid (32 gate-tiles, 4 K-splits).
// =============================================================
__global__ void __launch_bounds__(256) gates_mma(
    const float* __restrict__ W_ih, const float* __restrict__ W_hh)
{
    extern __shared__ char dsm[];
    const uint32_t sb = (smem_u32(dsm) + 127u) & ~127u;
    const int t = threadIdx.x, w = t >> 5, lane = t & 31;
    const int g = lane >> 2, tg = lane & 3;
    const int gbase = blockIdx.x * 128;
    const int ks_split = blockIdx.y;

    float acc[8][4] = {};
    float4 aP[8], bP[4];

    {
        const int kg = ks_split * 896;
        const bool ih = (kg < 2560);
#pragma unroll
        for (int i = 0; i < 8; i++) {
            int e = i * 256 + t, row = e >> 4, c4 = e & 15;
            int og = gbase + row;
            aP[i] = ih ? *(const float4*)(W_ih + (size_t)og * 2560 + kg + c4 * 4)
                       : *(const float4*)(W_hh + (size_t)og * 1024 + (kg - 2560) + c4 * 4);
        }
#pragma unroll
        for (int i = 0; i < 4; i++) {
            int e = i * 256 + t, row = e >> 4, c4 = e & 15;
            bP[i] = *(const float4*)(g_xfull + (size_t)row * XK + kg + c4 * 4);
        }
    }

    for (int ch = 0; ch < 14; ch++) {
        __syncthreads();
#pragma unroll
        for (int i = 0; i < 8; i++) {
            int e = i * 256 + t, row = e >> 4, c4 = e & 15;
            uint32_t ha, hb2, la, lb; split4(aP[i], ha, hb2, la, lb);
            uint32_t off = sw128((uint32_t)(row * 128 + c4 * 8));
            sts_v2(sb + T_A_HI + off, ha, hb2);
            sts_v2(sb + T_A_LO + off, la, lb);
        }
#pragma unroll
        for (int i = 0; i < 4; i++) {
            int e = i * 256 + t, row = e >> 4, c4 = e & 15;
            uint32_t ha, hb2, la, lb; split4(bP[i], ha, hb2, la, lb);
            uint32_t off = sw128((uint32_t)(row * 128 + c4 * 8));
            sts_v2(sb + T_B_HI + off, ha, hb2);
            sts_v2(sb + T_B_LO + off, la, lb);
        }
        __syncthreads();
        if (ch + 1 < 14) {
            const int kg = ks_split * 896 + (ch + 1) * 64;
            const bool ih = (kg < 2560);
#pragma unroll
            for (int i = 0; i < 8; i++) {
                int e = i * 256 + t, row = e >> 4, c4 = e & 15;
                int og = gbase + row;
                aP[i] = ih ? *(const float4*)(W_ih + (size_t)og * 2560 + kg + c4 * 4)
                           : *(const float4*)(W_hh + (size_t)og * 1024 + (kg - 2560) + c4 * 4);
            }
#pragma unroll
            for (int i = 0; i < 4; i++) {
                int e = i * 256 + t, row = e >> 4, c4 = e & 15;
                bP[i] = *(const float4*)(g_xfull + (size_t)row * XK + kg + c4 * 4);
            }
        }
#pragma unroll
        for (int ks = 0; ks < 4; ks++) {
            uint32_t ahi[4], alo[4];
            frag_a(sb + T_A_HI, w, g, tg, ks, ahi);
            frag_a(sb + T_A_LO, w, g, tg, ks, alo);
#pragma unroll
            for (int jh = 0; jh < 2; jh++) {
                uint32_t bh[4][2], bl[4][2];
#pragma unroll
                for (int jj = 0; jj < 4; jj++) {
                    frag_b(sb + T_B_HI, jh * 4 + jj, g, tg, ks, bh[jj]);
                    frag_b(sb + T_B_LO, jh * 4 + jj, g, tg, ks, bl[jj]);
                }
#pragma unroll
                for (int jj = 0; jj < 4; jj++) hmma(acc[jh * 4 + jj], ahi, bh[jj]);
#pragma unroll
                for (int jj = 0; jj < 4; jj++) hmma(acc[jh * 4 + jj], alo, bh[jj]);
#pragma unroll
                for (int jj = 0; jj < 4; jj++) hmma(acc[jh * 4 + jj], ahi, bl[jj]);
            }
        }
    }
    __syncthreads();
#pragma unroll
    for (int j = 0; j < 8; j++) {
#pragma unroll
        for (int k = 0; k < 4; k++) {
            int bb = 8 * j + 2 * tg + (k & 1);
            int vl = 16 * w + g + ((k >> 1) ? 8 : 0);
            sts32f(sb + (uint32_t)(bb * EPI_STRIDE + vl * 4), acc[j][k]);
        }
    }
    __syncthreads();
    float* gp = g_gparts + (size_t)ks_split * (Bv * G4H);
#pragma unroll
    for (int i = 0; i < 8; i++) {
        int e = i * 256 + t, bb = e >> 5, c4 = e & 31;
        float4 v = lds128f(sb + (uint32_t)(bb * EPI_STRIDE + c4 * 16));
        *(float4*)(gp + (size_t)bb * G4H + gbase + c4 * 4) = v;
    }
}

// =============================================================
// Kernel 4: split-K sum + biases + LSTM pointwise; also emits
// h_next as fp16 for the vocab GEMM. grid (4, B).
// =============================================================
__global__ void __launch_bounds__(256) lstm_kernel(
    const float* __restrict__ cell, const float* __restrict__ b_ih,
    const float* __restrict__ b_hh, float* __restrict__ out)
{
    const int b = blockIdx.y, h = blockIdx.x * 256 + threadIdx.x;
    float* h_out = out + (size_t)Bv * Vv;
    float* c_out = h_out + Bv * Hv;
    const int base = b * G4H;
    float gi = 0.f, gf = 0.f, gg = 0.f, go = 0.f;
#pragma unroll
    for (int ksv = 0; ksv < 4; ksv++) {
        const float* gp = g_gparts + (size_t)ksv * (Bv * G4H);
        gi += gp[base + h];
        gf += gp[base + 1024 + h];
        gg += gp[base + 2048 + h];
        go += gp[base + 3072 + h];
    }
    gi += b_ih[h]        + b_hh[h];
    gf += b_ih[1024 + h] + b_hh[1024 + h];
    gg += b_ih[2048 + h] + b_hh[2048 + h];
    go += b_ih[3072 + h] + b_hh[3072 + h];
    float si = 1.f / (1.f + expf(-gi));
    float sf = 1.f / (1.f + expf(-gf));
    float so = 1.f / (1.f + expf(-go));
    float c  = sf * cell[b * Hv + h] + si * tanhf(gg);
    float hn = so * tanhf(c);
    c_out[b * Hv + h] = c;
    h_out[b * Hv + h] = hn;
    g_hf16[b * Hv + h] = __float2half_rn(hn);
}

// =============================================================
// Kernel 5: vocab GEMM v6 — single-pass FP16. grid (393), 256 thr.
// A: coalesced float4 LDG -> regs -> fp16 cvt -> swizzled STS
//    (double-buffered; convert of ch+1 overlaps MMA of ch).
// B: fp16 via cp.async ring (pre-converted by lstm_kernel).
// 32 HMMA/warp/chunk (vs 96 in split-bf16). One sync per chunk.
// =============================================================
__global__ void __launch_bounds__(256) vocab_mma(
    const float* __restrict__ Wf, const float* __restrict__ bf,
    float* __restrict__ pred)
{
    extern __shared__ char dsm[];
    const uint32_t sb = (smem_u32(dsm) + 127u) & ~127u;
    const int t = threadIdx.x, w = t >> 5, lane = t & 31;
    const int g = lane >> 2, tg = lane & 3;
    const int vbase = blockIdx.x * 128;

    float acc[8][4] = {};
    float4 aP[8];

    // A chunk 0 -> regs (coalesced float4)
#pragma unroll
    for (int i = 0; i < 8; i++) {
        int e = i * 256 + t, row = e >> 4, c4 = e & 15;
        int vg = vbase + row;
        aP[i] = (vg < Vv) ? *(const float4*)(Wf + (size_t)vg * Hv + c4 * 4)
                          : make_float4(0.f, 0.f, 0.f, 0.f);
    }
    // B chunk 0 -> cp.async into B buf 0 (fp16, 8KB)
#pragma unroll
    for (int i = 0; i < 2; i++) {
        int e = i * 256 + t, n = e >> 3, seg = e & 7;
        uint32_t off = sw128((uint32_t)(n * 128 + seg * 16));
        cp16(sb + V_B(0) + off, g_hf16 + (size_t)n * Hv + seg * 8);
    }
    CP_COMMIT;
    // convert A chunk 0 -> A buf 0
#pragma unroll
    for (int i = 0; i < 8; i++) {
        int e = i * 256 + t, row = e >> 4, c4 = e & 15;
        uint32_t ha, hb2; cvt_h4(aP[i], ha, hb2);
        sts_v2(sb + V_A(0) + sw128((uint32_t)(row * 128 + c4 * 8)), ha, hb2);
    }
    CP_WAIT(0);
    __syncthreads();

    for (int ch = 0; ch < 16; ch++) {
        const uint32_t cur = (uint32_t)(ch & 1);
        const uint32_t nxt = cur ^ 1u;
        const uint32_t aT = sb + V_A(cur);
        const uint32_t bT = sb + V_B(cur);
        const bool more = (ch + 1 < 16);

        // LDG A(ch+1) into regs; cp.async B(ch+1) into nxt
        if (more) {
            const int kb = (ch + 1) * 64;
#pragma unroll
            for (int i = 0; i < 8; i++) {
                int e = i * 256 + t, row = e >> 4, c4 = e & 15;
                int vg = vbase + row;
                aP[i] = (vg < Vv)
                      ? *(const float4*)(Wf + (size_t)vg * Hv + kb + c4 * 4)
                      : make_float4(0.f, 0.f, 0.f, 0.f);
            }
#pragma unroll
            for (int i = 0; i < 2; i++) {
                int e = i * 256 + t, n = e >> 3, seg = e & 7;
                uint32_t off = sw128((uint32_t)(n * 128 + seg * 16));
                cp16(sb + V_B(nxt) + off, g_hf16 + (size_t)n * Hv + kb + seg * 8);
            }
            CP_COMMIT;
        }

        // MMA on cur buffers: 4 ks x 8 j = 32 fp16 HMMA
#pragma unroll
        for (int ks = 0; ks < 4; ks++) {
            uint32_t a[4];
            frag_a(aT, w, g, tg, ks, a);
#pragma unroll
            for (int j = 0; j < 8; j++) {
                uint32_t b2[2];
                frag_b(bT, j, g, tg, ks, b2);
                fmma(acc[j], a, b2);
            }
        }

        // convert A(ch+1) -> nxt A buffer (overlaps MMA issue slots)
        if (more) {
#pragma unroll
            for (int i = 0; i < 8; i++) {
                int e = i * 256 + t, row = e >> 4, c4 = e & 15;
                uint32_t ha, hb2; cvt_h4(aP[i], ha, hb2);
                sts_v2(sb + V_A(nxt) + sw128((uint32_t)(row * 128 + c4 * 8)), ha, hb2);
            }
        }
        CP_WAIT(0);
        __syncthreads();
    }

    // epilogue: transpose via smem (reuses tile space), add bias, STG
    // (pred row stride Vv=50257 not 16B-aligned -> scalar stores)
#pragma unroll
    for (int j = 0; j < 8; j++) {
#pragma unroll
        for (int k = 0; k < 4; k++) {
            int bb = 8 * j + 2 * tg + (k & 1);
            int vl = 16 * w + g + ((k >> 1) ? 8 : 0);
            sts32f(sb + (uint32_t)(bb * EPI_STRIDE + vl * 4), acc[j][k]);
        }
    }
    __syncthreads();
#pragma unroll
    for (int i = 0; i < 8; i++) {
        int e = i * 256 + t, bb = e >> 5, c4 = e & 31;
        float4 v = lds128f(sb + (uint32_t)(bb * EPI_STRIDE + c4 * 16));
        int vg = vbase + c4 * 4;
        float* prow = pred + (size_t)bb * Vv;
        float vv[4] = {v.x, v.y, v.z, v.w};
#pragma unroll
        for (int d = 0; d < 4; d++)
            if (vg + d < Vv) prow[vg + d] = vv[d] + bf[vg + d];
    }
}

// =============================================================
extern "C" void kernel_launch(void* const* d_in, const int* in_sizes, int n_in,
                              void* d_out, int out_size)
{
    const float* enc    = (const float*)d_in[0];
    const int*   x_tok  = (const int*)  d_in[1];
    const float* hidden = (const float*)d_in[2];
    const float* cell   = (const float*)d_in[3];
    const float* emb    = (const float*)d_in[4];
    const float* We     = (const float*)d_in[5];
    const float* be     = (const float*)d_in[6];
    const float* W_ih   = (const float*)d_in[7];
    const float* W_hh   = (const float*)d_in[8];
    const float* b_ih   = (const float*)d_in[9];
    const float* b_hh   = (const float*)d_in[10];
    const float* Wf     = (const float*)d_in[11];
    const float* bf     = (const float*)d_in[12];

    float* out   = (float*)d_out;
    float* pred  = out;                          // [B, V]

    cudaFuncSetAttribute(gates_mma, cudaFuncAttributeMaxDynamicSharedMemorySize, SMEM_DYN);
    cudaFuncSetAttribute(vocab_mma, cudaFuncAttributeMaxDynamicSharedMemorySize, SMEM_VOC);

    hbias_kernel  <<<Bv, 256>>>(hidden, We, be);
    xemb_kernel   <<<Bv, 256>>>(emb, x_tok);
    xhid_kernel   <<<Bv, 256>>>(hidden);
    attn_kernel   <<<dim3(SPLITS, Bv), 256>>>(enc, We);
    combine_kernel<<<dim3(8, Bv), 256>>>();
    gates_mma     <<<dim3(32, 4), 256, SMEM_DYN>>>(W_ih, W_hh);
    lstm_kernel   <<<dim3(4, Bv), 256>>>(cell, b_ih, b_hh, out);
    vocab_mma     <<<(Vv + 127) / 128, 256, SMEM_VOC>>>(Wf, bf, pred);
}

// round 12
// speedup vs baseline: 1.2153x; 1.0022x over previous
#include <cuda_runtime.h>
#include <cuda_bf16.h>
#include <cuda_fp16.h>
#include <cstdint>
#include <math.h>

#define Bv   64
#define Sv   1024
#define Hv   1024
#define Ev   512
#define Vv   50257
#define D2H  2048
#define XK   3584   // 2H + E + H
#define G4H  4096
#define SPLITS 8

// ---------------- scratch (device globals; no runtime allocation) ----------
__device__ float g_hbias[Bv];
__device__ float g_partial_l[Bv * SPLITS];
__device__ float g_partial_acc[(size_t)Bv * SPLITS * D2H];   // 4 MB
__device__ float g_xfull[Bv * XK];
__device__ float g_gparts[4 * (size_t)Bv * G4H];              // 4 MB
__device__ __half g_hf16[Bv * Hv];                            // h_next fp16

// =================== helpers (base PTX only, no sm_103a features) ==========
__device__ __forceinline__ uint32_t smem_u32(const void* p) {
    uint32_t a;
    asm("{ .reg .u64 tmp; cvta.to.shared.u64 tmp, %1; cvt.u32.u64 %0, tmp; }"
        : "=r"(a) : "l"(p));
    return a;
}
__device__ __forceinline__ uint32_t lds32(uint32_t addr) {
    uint32_t v;
    asm volatile("ld.shared.b32 %0, [%1];" : "=r"(v) : "r"(addr));
    return v;
}
__device__ __forceinline__ void sts_v2(uint32_t addr, uint32_t a, uint32_t b) {
    asm volatile("st.shared.v2.b32 [%0], {%1, %2};" :: "r"(addr), "r"(a), "r"(b));
}
__device__ __forceinline__ void sts32f(uint32_t addr, float v) {
    asm volatile("st.shared.f32 [%0], %1;" :: "r"(addr), "f"(v));
}
__device__ __forceinline__ float4 lds128f(uint32_t addr) {
    float4 v;
    asm volatile("ld.shared.v4.f32 {%0,%1,%2,%3}, [%4];"
        : "=f"(v.x), "=f"(v.y), "=f"(v.z), "=f"(v.w) : "r"(addr));
    return v;
}
__device__ __forceinline__ void cp16(uint32_t dst, const void* src) {
    asm volatile("cp.async.cg.shared.global [%0], [%1], 16;"
        :: "r"(dst), "l"(src) : "memory");
}
#define CP_COMMIT  asm volatile("cp.async.commit_group;" ::: "memory")
#define CP_WAIT(n) asm volatile("cp.async.wait_group %0;" :: "n"(n) : "memory")
#define LDSM_X4(r0, r1, r2, r3, addr) \
    asm volatile("ldmatrix.sync.aligned.m8n8.x4.shared.b16 {%0,%1,%2,%3}, [%4];" \
        : "=r"(r0), "=r"(r1), "=r"(r2), "=r"(r3) : "r"(addr))

__device__ __forceinline__ uint32_t sw128(uint32_t off) {
    return off ^ ((off >> 3) & 0x70);
}
// m16n8k16 bf16 MMA, f32 accum (base PTX, sm_80+)
__device__ __forceinline__ void hmma(float* c, const uint32_t* a, const uint32_t* b) {
    asm volatile(
        "mma.sync.aligned.m16n8k16.row.col.f32.bf16.bf16.f32 "
        "{%0,%1,%2,%3}, {%4,%5,%6,%7}, {%8,%9}, {%0,%1,%2,%3};"
        : "+f"(c[0]), "+f"(c[1]), "+f"(c[2]), "+f"(c[3])
        : "r"(a[0]), "r"(a[1]), "r"(a[2]), "r"(a[3]), "r"(b[0]), "r"(b[1]));
}
// m16n8k16 fp16 MMA, f32 accum (base PTX, sm_80+)
__device__ __forceinline__ void fmma(float* c, uint32_t a0, uint32_t a1,
                                     uint32_t a2, uint32_t a3,
                                     uint32_t b0, uint32_t b1) {
    asm volatile(
        "mma.sync.aligned.m16n8k16.row.col.f32.f16.f16.f32 "
        "{%0,%1,%2,%3}, {%4,%5,%6,%7}, {%8,%9}, {%0,%1,%2,%3};"
        : "+f"(c[0]), "+f"(c[1]), "+f"(c[2]), "+f"(c[3])
        : "r"(a0), "r"(a1), "r"(a2), "r"(a3), "r"(b0), "r"(b1));
}
// fp32x4 -> bf16 hi pair + lo (residual) pair (gates kernel)
__device__ __forceinline__ void split4(float4 v, uint32_t& ha, uint32_t& hb,
                                       uint32_t& la, uint32_t& lb) {
    asm("cvt.rn.bf16x2.f32 %0, %1, %2;" : "=r"(ha) : "f"(v.y), "f"(v.x));
    asm("cvt.rn.bf16x2.f32 %0, %1, %2;" : "=r"(hb) : "f"(v.w), "f"(v.z));
    float rx = v.x - __uint_as_float(ha << 16);
    float ry = v.y - __uint_as_float(ha & 0xffff0000u);
    float rz = v.z - __uint_as_float(hb << 16);
    float rw = v.w - __uint_as_float(hb & 0xffff0000u);
    asm("cvt.rn.bf16x2.f32 %0, %1, %2;" : "=r"(la) : "f"(ry), "f"(rx));
    asm("cvt.rn.bf16x2.f32 %0, %1, %2;" : "=r"(lb) : "f"(rw), "f"(rz));
}
// fp32x4 -> fp16x2 pair (vocab kernel)
__device__ __forceinline__ void cvt_h4(float4 v, uint32_t& ha, uint32_t& hb) {
    asm("cvt.rn.f16x2.f32 %0, %1, %2;" : "=r"(ha) : "f"(v.y), "f"(v.x));
    asm("cvt.rn.f16x2.f32 %0, %1, %2;" : "=r"(hb) : "f"(v.w), "f"(v.z));
}

// gates kernel smem tile layout (bytes from aligned dynamic base)
#define T_A_HI 0
#define T_A_LO 16384
#define T_B_HI 32768
#define T_B_LO 40960
#define SMEM_DYN 49408
#define EPI_STRIDE 528          // 132 floats, 16B-aligned transpose stride

// vocab smem: fp16 double-buffered A (2 x 16KB) + B (2 x 8KB)
#define V_A(c) ((uint32_t)(c) * 16384u)
#define V_B(c) (32768u + (uint32_t)(c) * 8192u)
#define SMEM_VOC 49408

// =============================================================
// Kernel 0: fused prep. grid (B). hbias + emb->xfull + hidden->xfull.
// =============================================================
__global__ void __launch_bounds__(256) prep_kernel(
    const float* __restrict__ hidden, const float* __restrict__ We,
    const float* __restrict__ be_p, const float* __restrict__ emb,
    const int* __restrict__ x_tok)
{
    const int b = blockIdx.x, t = threadIdx.x;
    const int lane = t & 31, wid = t >> 5;
    __shared__ float red[8];
    // hbias
    {
        float4 hv = ((const float4*)hidden)[b * 256 + t];
        float4 wv = ((const float4*)We)[512 + t];
        float p = hv.x * wv.x + hv.y * wv.y + hv.z * wv.z + hv.w * wv.w;
#pragma unroll
        for (int o = 16; o > 0; o >>= 1) p += __shfl_xor_sync(0xffffffffu, p, o);
        if (lane == 0) red[wid] = p;
    }
    __syncthreads();
    if (t == 0) {
        float s = be_p[0];
#pragma unroll
        for (int w = 0; w < 8; w++) s += red[w];
        g_hbias[b] = s;
    }
    // emb -> xfull tail
    const int tok = x_tok[b];
    for (int j = t; j < Ev; j += 256)
        g_xfull[b * XK + D2H + j] = emb[(size_t)tok * Ev + j];
    // hidden -> xfull tail
    for (int j = t; j < Hv; j += 256)
        g_xfull[b * XK + D2H + Ev + j] = hidden[b * Hv + j];
}

// =============================================================
// Kernel 1: attention. grid (SPLITS=8, B), 256 thr, 128 rows/CTA.
// 4-row tiles, register double-buffered loads, 1 sync/tile.
// Unnormalized softmax (relu energy >= 0, bounded; exp safe).
// =============================================================
__device__ __forceinline__ void attn_load(float4 ev[8], const float4* tbase, int t) {
#pragma unroll
    for (int r = 0; r < 4; r++) {
        ev[2 * r]     = tbase[r * 512 + t];
        ev[2 * r + 1] = tbase[r * 512 + 256 + t];
    }
}
__global__ void __launch_bounds__(256) attn_kernel(
    const float* __restrict__ enc, const float* __restrict__ We)
{
    const int b = blockIdx.y, sp = blockIdx.x, t = threadIdx.x;
    const int lane = t & 31, wid = t >> 5;
    __shared__ float red[2][8][4];

    const float4* We4 = (const float4*)We;
    const float4 w0 = We4[t];
    const float4 w1 = We4[256 + t];
    const float hb = g_hbias[b];

    float acc[8] = {0.f, 0.f, 0.f, 0.f, 0.f, 0.f, 0.f, 0.f};
    float lsum = 0.f;
    const float4* encb = (const float4*)enc + ((size_t)(b * Sv + sp * 128)) * 512;

    float4 evA[8], evB[8];
    attn_load(evA, encb, t);

#define ATTN_PROC(BUF, TILE_EXPR)                                              \
    {                                                                          \
        const int tile = (TILE_EXPR);                                          \
        const int par = tile & 1;                                              \
        float d[4];                                                            \
        _Pragma("unroll")                                                      \
        for (int r = 0; r < 4; r++) {                                          \
            d[r] = BUF[2*r].x * w0.x + BUF[2*r].y * w0.y                       \
                 + BUF[2*r].z * w0.z + BUF[2*r].w * w0.w                       \
                 + BUF[2*r+1].x * w1.x + BUF[2*r+1].y * w1.y                   \
                 + BUF[2*r+1].z * w1.z + BUF[2*r+1].w * w1.w;                  \
            _Pragma("unroll")                                                  \
            for (int o = 16; o > 0; o >>= 1)                                   \
                d[r] += __shfl_xor_sync(0xffffffffu, d[r], o);                 \
        }                                                                      \
        if (lane == 0) {                                                       \
            _Pragma("unroll")                                                  \
            for (int r = 0; r < 4; r++) red[par][wid][r] = d[r];               \
        }                                                                      \
        __syncthreads();                                                       \
        _Pragma("unroll")                                                      \
        for (int r = 0; r < 4; r++) {                                          \
            float s = hb;                                                      \
            _Pragma("unroll")                                                  \
            for (int w2 = 0; w2 < 8; w2++) s += red[par][w2][r];               \
            s = fmaxf(s, 0.f);                                                 \
            float wgt = __expf(s);                                             \
            lsum += wgt;                                                       \
            acc[0] += wgt * BUF[2*r].x;   acc[1] += wgt * BUF[2*r].y;          \
            acc[2] += wgt * BUF[2*r].z;   acc[3] += wgt * BUF[2*r].w;          \
            acc[4] += wgt * BUF[2*r+1].x; acc[5] += wgt * BUF[2*r+1].y;        \
            acc[6] += wgt * BUF[2*r+1].z; acc[7] += wgt * BUF[2*r+1].w;        \
        }                                                                      \
    }

    for (int tp = 0; tp < 16; tp++) {
        attn_load(evB, encb + (size_t)(2 * tp + 1) * 4 * 512, t);
        ATTN_PROC(evA, 2 * tp);
        if (tp < 15)
            attn_load(evA, encb + (size_t)(2 * tp + 2) * 4 * 512, t);
        ATTN_PROC(evB, 2 * tp + 1);
    }
#undef ATTN_PROC

    float4* pacc = (float4*)(g_partial_acc + ((size_t)(b * SPLITS + sp)) * D2H);
    pacc[t]       = make_float4(acc[0], acc[1], acc[2], acc[3]);
    pacc[256 + t] = make_float4(acc[4], acc[5], acc[6], acc[7]);
    if (t == 0) g_partial_l[b * SPLITS + sp] = lsum;
}

// =============================================================
// Kernel 2: combine partials -> c_i (head of x_full). grid (8, B).
// =============================================================
__global__ void __launch_bounds__(256) combine_kernel()
{
    const int q = blockIdx.x, b = blockIdx.y, t = threadIdx.x;
    float s = 0.f;
#pragma unroll
    for (int i = 0; i < SPLITS; i++) s += g_partial_l[b * SPLITS + i];
    const float inv = 1.f / s;
    const int c = q * 256 + t;
    float a = 0.f;
#pragma unroll
    for (int i = 0; i < SPLITS; i++)
        a += g_partial_acc[((size_t)(b * SPLITS + i)) * D2H + c];
    g_xfull[b * XK + c] = a * inv;
}

// ============= bf16 fragment loaders (gates kernel) ===============
__device__ __forceinline__ void frag_a(uint32_t tile, int w, int g, int tg,
                                       int ks, uint32_t a[4]) {
    uint32_t r0 = (uint32_t)(16 * w + g);
    uint32_t k0 = (uint32_t)((16 * ks + 2 * tg) * 2);
    a[0] = lds32(tile + sw128(r0 * 128 + k0));
    a[1] = lds32(tile + sw128((r0 + 8) * 128 + k0));
    a[2] = lds32(tile + sw128(r0 * 128 + k0 + 16));
    a[3] = lds32(tile + sw128((r0 + 8) * 128 + k0 + 16));
}
__device__ __forceinline__ void frag_b(uint32_t tile, int j, int g, int tg,
                                       int ks, uint32_t bfr[2]) {
    uint32_t n = (uint32_t)(8 * j + g);
    uint32_t k0 = (uint32_t)((16 * ks + 2 * tg) * 2);
    bfr[0] = lds32(tile + sw128(n * 128 + k0));
    bfr[1] = lds32(tile + sw128(n * 128 + k0 + 16));
}

// =============================================================
// Kernel 3: gates GEMM (HMMA split-bf16). grid (32 gate-tiles, 4 K-splits).
// =============================================================
__global__ void __launch_bounds__(256) gates_mma(
    const float* __restrict__ W_ih, const float* __restrict__ W_hh)
{
    extern __shared__ char dsm[];
    const uint32_t sb = (smem_u32(dsm) + 127u) & ~127u;
    const int t = threadIdx.x, w = t >> 5, lane = t & 31;
    const int g = lane >> 2, tg = lane & 3;
    const int gbase = blockIdx.x * 128;
    const int ks_split = blockIdx.y;

    float acc[8][4] = {};
    float4 aP[8], bP[4];

    {
        const int kg = ks_split * 896;
        const bool ih = (kg < 2560);
#pragma unroll
        for (int i = 0; i < 8; i++) {
            int e = i * 256 + t, row = e >> 4, c4 = e & 15;
            int og = gbase + row;
            aP[i] = ih ? *(const float4*)(W_ih + (size_t)og * 2560 + kg + c4 * 4)
                       : *(const float4*)(W_hh + (size_t)og * 1024 + (kg - 2560) + c4 * 4);
        }
#pragma unroll
        for (int i = 0; i < 4; i++) {
            int e = i * 256 + t, row = e >> 4, c4 = e & 15;
            bP[i] = *(const float4*)(g_xfull + (size_t)row * XK + kg + c4 * 4);
        }
    }

    for (int ch = 0; ch < 14; ch++) {
        __syncthreads();
#pragma unroll
        for (int i = 0; i < 8; i++) {
            int e = i * 256 + t, row = e >> 4, c4 = e & 15;
            uint32_t ha, hb2, la, lb; split4(aP[i], ha, hb2, la, lb);
            uint32_t off = sw128((uint32_t)(row * 128 + c4 * 8));
            sts_v2(sb + T_A_HI + off, ha, hb2);
            sts_v2(sb + T_A_LO + off, la, lb);
        }
#pragma unroll
        for (int i = 0; i < 4; i++) {
            int e = i * 256 + t, row = e >> 4, c4 = e & 15;
            uint32_t ha, hb2, la, lb; split4(bP[i], ha, hb2, la, lb);
            uint32_t off = sw128((uint32_t)(row * 128 + c4 * 8));
            sts_v2(sb + T_B_HI + off, ha, hb2);
            sts_v2(sb + T_B_LO + off, la, lb);
        }
        __syncthreads();
        if (ch + 1 < 14) {
            const int kg = ks_split * 896 + (ch + 1) * 64;
            const bool ih = (kg < 2560);
#pragma unroll
            for (int i = 0; i < 8; i++) {
                int e = i * 256 + t, row = e >> 4, c4 = e & 15;
                int og = gbase + row;
                aP[i] = ih ? *(const float4*)(W_ih + (size_t)og * 2560 + kg + c4 * 4)
                           : *(const float4*)(W_hh + (size_t)og * 1024 + (kg - 2560) + c4 * 4);
            }
#pragma unroll
            for (int i = 0; i < 4; i++) {
                int e = i * 256 + t, row = e >> 4, c4 = e & 15;
                bP[i] = *(const float4*)(g_xfull + (size_t)row * XK + kg + c4 * 4);
            }
        }
#pragma unroll
        for (int ks = 0; ks < 4; ks++) {
            uint32_t ahi[4], alo[4];
            frag_a(sb + T_A_HI, w, g, tg, ks, ahi);
            frag_a(sb + T_A_LO, w, g, tg, ks, alo);
#pragma unroll
            for (int jh = 0; jh < 2; jh++) {
                uint32_t bh[4][2], bl[4][2];
#pragma unroll
                for (int jj = 0; jj < 4; jj++) {
                    frag_b(sb + T_B_HI, jh * 4 + jj, g, tg, ks, bh[jj]);
                    frag_b(sb + T_B_LO, jh * 4 + jj, g, tg, ks, bl[jj]);
                }
#pragma unroll
                for (int jj = 0; jj < 4; jj++) hmma(acc[jh * 4 + jj], ahi, bh[jj]);
#pragma unroll
                for (int jj = 0; jj < 4; jj++) hmma(acc[jh * 4 + jj], alo, bh[jj]);
#pragma unroll
                for (int jj = 0; jj < 4; jj++) hmma(acc[jh * 4 + jj], ahi, bl[jj]);
            }
        }
    }
    __syncthreads();
#pragma unroll
    for (int j = 0; j < 8; j++) {
#pragma unroll
        for (int k = 0; k < 4; k++) {
            int bb = 8 * j + 2 * tg + (k & 1);
            int vl = 16 * w + g + ((k >> 1) ? 8 : 0);
            sts32f(sb + (uint32_t)(bb * EPI_STRIDE + vl * 4), acc[j][k]);
        }
    }
    __syncthreads();
    float* gp = g_gparts + (size_t)ks_split * (Bv * G4H);
#pragma unroll
    for (int i = 0; i < 8; i++) {
        int e = i * 256 + t, bb = e >> 5, c4 = e & 31;
        float4 v = lds128f(sb + (uint32_t)(bb * EPI_STRIDE + c4 * 16));
        *(float4*)(gp + (size_t)bb * G4H + gbase + c4 * 4) = v;
    }
}

// =============================================================
// Kernel 4: split-K sum + biases + LSTM pointwise; emits fp16 h.
// grid (4, B).
// =============================================================
__global__ void __launch_bounds__(256) lstm_kernel(
    const float* __restrict__ cell, const float* __restrict__ b_ih,
    const float* __restrict__ b_hh, float* __restrict__ out)
{
    const int b = blockIdx.y, h = blockIdx.x * 256 + threadIdx.x;
    float* h_out = out + (size_t)Bv * Vv;
    float* c_out = h_out + Bv * Hv;
    const int base = b * G4H;
    float gi = 0.f, gf = 0.f, gg = 0.f, go = 0.f;
#pragma unroll
    for (int ksv = 0; ksv < 4; ksv++) {
        const float* gp = g_gparts + (size_t)ksv * (Bv * G4H);
        gi += gp[base + h];
        gf += gp[base + 1024 + h];
        gg += gp[base + 2048 + h];
        go += gp[base + 3072 + h];
    }
    gi += b_ih[h]        + b_hh[h];
    gf += b_ih[1024 + h] + b_hh[1024 + h];
    gg += b_ih[2048 + h] + b_hh[2048 + h];
    go += b_ih[3072 + h] + b_hh[3072 + h];
    float si = 1.f / (1.f + expf(-gi));
    float sf = 1.f / (1.f + expf(-gf));
    float so = 1.f / (1.f + expf(-go));
    float c  = sf * cell[b * Hv + h] + si * tanhf(gg);
    float hn = so * tanhf(c);
    c_out[b * Hv + h] = c;
    h_out[b * Hv + h] = hn;
    g_hf16[b * Hv + h] = __float2half_rn(hn);
}

// =============================================================
// Kernel 5: vocab GEMM v7 — fp16 + ldmatrix. grid (393), 256 thr.
// A: coalesced float4 LDG -> regs -> fp16 cvt -> swizzled STS.
// B: fp16 via cp.async ring. Fragments via ldmatrix.x4:
//   1 A-ldsm + 4 B-ldsm per ks (20/warp/chunk vs 80 lds32).
// =============================================================
__global__ void __launch_bounds__(256) vocab_mma(
    const float* __restrict__ Wf, const float* __restrict__ bf,
    float* __restrict__ pred)
{
    extern __shared__ char dsm[];
    const uint32_t sb = (smem_u32(dsm) + 127u) & ~127u;
    const int t = threadIdx.x, w = t >> 5, lane = t & 31;
    const int g = lane >> 2, tg = lane & 3;
    const int vbase = blockIdx.x * 128;

    // ldmatrix per-lane addressing: seg = which 8x8 matrix, rsel = row in it
    const int seg = lane >> 3, rsel = lane & 7;
    const uint32_t kx   = (uint32_t)((seg >> 1) * 16);      // k-byte offset (0/16)
    const uint32_t xorv = (uint32_t)(rsel << 4);            // sw128 row xor
    const uint32_t arow = (uint32_t)(16 * w + (seg & 1) * 8 + rsel);
    const uint32_t abase = arow * 128;
    const uint32_t nb0   = (uint32_t)(((seg & 1) * 8 + rsel) * 128);

    float acc[8][4] = {};
    float4 aP[8];

    // A chunk 0 -> regs (coalesced float4)
#pragma unroll
    for (int i = 0; i < 8; i++) {
        int e = i * 256 + t, row = e >> 4, c4 = e & 15;
        int vg = vbase + row;
        aP[i] = (vg < Vv) ? *(const float4*)(Wf + (size_t)vg * Hv + c4 * 4)
                          : make_float4(0.f, 0.f, 0.f, 0.f);
    }
    // B chunk 0 -> cp.async into B buf 0 (fp16, 8KB)
#pragma unroll
    for (int i = 0; i < 2; i++) {
        int e = i * 256 + t, n = e >> 3, sg = e & 7;
        uint32_t off = sw128((uint32_t)(n * 128 + sg * 16));
        cp16(sb + V_B(0) + off, g_hf16 + (size_t)n * Hv + sg * 8);
    }
    CP_COMMIT;
    // convert A chunk 0 -> A buf 0
#pragma unroll
    for (int i = 0; i < 8; i++) {
        int e = i * 256 + t, row = e >> 4, c4 = e & 15;
        uint32_t ha, hb2; cvt_h4(aP[i], ha, hb2);
        sts_v2(sb + V_A(0) + sw128((uint32_t)(row * 128 + c4 * 8)), ha, hb2);
    }
    CP_WAIT(0);
    __syncthreads();

    for (int ch = 0; ch < 16; ch++) {
        const uint32_t cur = (uint32_t)(ch & 1);
        const uint32_t nxt = cur ^ 1u;
        const uint32_t aT = sb + V_A(cur);
        const uint32_t bT = sb + V_B(cur);
        const bool more = (ch + 1 < 16);

        // LDG A(ch+1) into regs; cp.async B(ch+1) into nxt
        if (more) {
            const int kb = (ch + 1) * 64;
#pragma unroll
            for (int i = 0; i < 8; i++) {
                int e = i * 256 + t, row = e >> 4, c4 = e & 15;
                int vg = vbase + row;
                aP[i] = (vg < Vv)
                      ? *(const float4*)(Wf + (size_t)vg * Hv + kb + c4 * 4)
                      : make_float4(0.f, 0.f, 0.f, 0.f);
            }
#pragma unroll
            for (int i = 0; i < 2; i++) {
                int e = i * 256 + t, n = e >> 3, sg = e & 7;
                uint32_t off = sw128((uint32_t)(n * 128 + sg * 16));
                cp16(sb + V_B(nxt) + off, g_hf16 + (size_t)n * Hv + kb + sg * 8);
            }
            CP_COMMIT;
        }

        // MMA on cur buffers via ldmatrix: per ks, 1 A-ldsm + 4 B-ldsm
#pragma unroll
        for (int ks = 0; ks < 4; ks++) {
            const uint32_t kb2 = ((uint32_t)(ks * 32) + kx) ^ xorv;
            uint32_t a0, a1, a2, a3;
            LDSM_X4(a0, a1, a2, a3, aT + abase + kb2);
#pragma unroll
            for (int u = 0; u < 4; u++) {
                uint32_t m0, m1, m2, m3;
                LDSM_X4(m0, m1, m2, m3, bT + (uint32_t)(u * 2048) + nb0 + kb2);
                fmma(acc[2 * u],     a0, a1, a2, a3, m0, m2);
                fmma(acc[2 * u + 1], a0, a1, a2, a3, m1, m3);
            }
        }

        // convert A(ch+1) -> nxt A buffer (overlaps MMA issue slots)
        if (more) {
#pragma unroll
            for (int i = 0; i < 8; i++) {
                int e = i * 256 + t, row = e >> 4, c4 = e & 15;
                uint32_t ha, hb2; cvt_h4(aP[i], ha, hb2);
                sts_v2(sb + V_A(nxt) + sw128((uint32_t)(row * 128 + c4 * 8)), ha, hb2);
            }
        }
        CP_WAIT(0);
        __syncthreads();
    }

    // epilogue: transpose via smem (reuses tile space), add bias, STG
    // (pred row stride Vv=50257 not 16B-aligned -> scalar stores)
#pragma unroll
    for (int j = 0; j < 8; j++) {
#pragma unroll
        for (int k = 0; k < 4; k++) {
            int bb = 8 * j + 2 * tg + (k & 1);
            int vl = 16 * w + g + ((k >> 1) ? 8 : 0);
            sts32f(sb + (uint32_t)(bb * EPI_STRIDE + vl * 4), acc[j][k]);
        }
    }
    __syncthreads();
#pragma unroll
    for (int i = 0; i < 8; i++) {
        int e = i * 256 + t, bb = e >> 5, c4 = e & 31;
        float4 v = lds128f(sb + (uint32_t)(bb * EPI_STRIDE + c4 * 16));
        int vg = vbase + c4 * 4;
        float* prow = pred + (size_t)bb * Vv;
        float vv[4] = {v.x, v.y, v.z, v.w};
#pragma unroll
        for (int d = 0; d < 4; d++)
            if (vg + d < Vv) prow[vg + d] = vv[d] + bf[vg + d];
    }
}

// =============================================================
extern "C" void kernel_launch(void* const* d_in, const int* in_sizes, int n_in,
                              void* d_out, int out_size)
{
    const float* enc    = (const float*)d_in[0];
    const int*   x_tok  = (const int*)  d_in[1];
    const float* hidden = (const float*)d_in[2];
    const float* cell   = (const float*)d_in[3];
    const float* emb    = (const float*)d_in[4];
    const float* We     = (const float*)d_in[5];
    const float* be     = (const float*)d_in[6];
    const float* W_ih   = (const float*)d_in[7];
    const float* W_hh   = (const float*)d_in[8];
    const float* b_ih   = (const float*)d_in[9];
    const float* b_hh   = (const float*)d_in[10];
    const float* Wf     = (const float*)d_in[11];
    const float* bf     = (const float*)d_in[12];

    float* out   = (float*)d_out;
    float* pred  = out;                          // [B, V]

    cudaFuncSetAttribute(gates_mma, cudaFuncAttributeMaxDynamicSharedMemorySize, SMEM_DYN);
    cudaFuncSetAttribute(vocab_mma, cudaFuncAttributeMaxDynamicSharedMemorySize, SMEM_VOC);

    prep_kernel   <<<Bv, 256>>>(hidden, We, be, emb, x_tok);
    attn_kernel   <<<dim3(SPLITS, Bv), 256>>>(enc, We);
    combine_kernel<<<dim3(8, Bv), 256>>>();
    gates_mma     <<<dim3(32, 4), 256, SMEM_DYN>>>(W_ih, W_hh);
    lstm_kernel   <<<dim3(4, Bv), 256>>>(cell, b_ih, b_hh, out);
    vocab_mma     <<<(Vv + 127) / 128, 256, SMEM_VOC>>>(Wf, bf, pred);
}

// round 13
// speedup vs baseline: 1.2792x; 1.0526x over previous
#include <cuda_runtime.h>
#include <cuda_bf16.h>
#include <cuda_fp16.h>
#include <cstdint>
#include <math.h>

#define Bv   64
#define Sv   1024
#define Hv   1024
#define Ev   512
#define Vv   50257
#define D2H  2048
#define XK   3584   // 2H + E + H
#define G4H  4096
#define SPLITS 8

// ---------------- scratch (device globals; no runtime allocation) ----------
__device__ float g_hbias[Bv];
__device__ float g_partial_l[Bv * SPLITS];
__device__ float g_partial_acc[(size_t)Bv * SPLITS * D2H];   // 4 MB
__device__ __half g_xf16[Bv * XK];                            // x_full fp16
__device__ float g_gparts[4 * (size_t)Bv * G4H];              // 4 MB
__device__ __half g_hf16[Bv * Hv];                            // h_next fp16

// =================== helpers (base PTX only, no sm_103a features) ==========
__device__ __forceinline__ uint32_t smem_u32(const void* p) {
    uint32_t a;
    asm("{ .reg .u64 tmp; cvta.to.shared.u64 tmp, %1; cvt.u32.u64 %0, tmp; }"
        : "=r"(a) : "l"(p));
    return a;
}
__device__ __forceinline__ uint32_t lds32(uint32_t addr) {
    uint32_t v;
    asm volatile("ld.shared.b32 %0, [%1];" : "=r"(v) : "r"(addr));
    return v;
}
__device__ __forceinline__ void sts_v2(uint32_t addr, uint32_t a, uint32_t b) {
    asm volatile("st.shared.v2.b32 [%0], {%1, %2};" :: "r"(addr), "r"(a), "r"(b));
}
__device__ __forceinline__ void sts32f(uint32_t addr, float v) {
    asm volatile("st.shared.f32 [%0], %1;" :: "r"(addr), "f"(v));
}
__device__ __forceinline__ float4 lds128f(uint32_t addr) {
    float4 v;
    asm volatile("ld.shared.v4.f32 {%0,%1,%2,%3}, [%4];"
        : "=f"(v.x), "=f"(v.y), "=f"(v.z), "=f"(v.w) : "r"(addr));
    return v;
}
__device__ __forceinline__ void cp16(uint32_t dst, const void* src) {
    asm volatile("cp.async.cg.shared.global [%0], [%1], 16;"
        :: "r"(dst), "l"(src) : "memory");
}
#define CP_COMMIT  asm volatile("cp.async.commit_group;" ::: "memory")
#define CP_WAIT(n) asm volatile("cp.async.wait_group %0;" :: "n"(n) : "memory")
#define LDSM_X4(r0, r1, r2, r3, addr) \
    asm volatile("ldmatrix.sync.aligned.m8n8.x4.shared.b16 {%0,%1,%2,%3}, [%4];" \
        : "=r"(r0), "=r"(r1), "=r"(r2), "=r"(r3) : "r"(addr))

__device__ __forceinline__ uint32_t sw128(uint32_t off) {
    return off ^ ((off >> 3) & 0x70);
}
// m16n8k16 fp16 MMA, f32 accum (base PTX, sm_80+)
__device__ __forceinline__ void fmma(float* c, uint32_t a0, uint32_t a1,
                                     uint32_t a2, uint32_t a3,
                                     uint32_t b0, uint32_t b1) {
    asm volatile(
        "mma.sync.aligned.m16n8k16.row.col.f32.f16.f16.f32 "
        "{%0,%1,%2,%3}, {%4,%5,%6,%7}, {%8,%9}, {%0,%1,%2,%3};"
        : "+f"(c[0]), "+f"(c[1]), "+f"(c[2]), "+f"(c[3])
        : "r"(a0), "r"(a1), "r"(a2), "r"(a3), "r"(b0), "r"(b1));
}
// fp32x4 -> fp16x2 pair
__device__ __forceinline__ void cvt_h4(float4 v, uint32_t& ha, uint32_t& hb) {
    asm("cvt.rn.f16x2.f32 %0, %1, %2;" : "=r"(ha) : "f"(v.y), "f"(v.x));
    asm("cvt.rn.f16x2.f32 %0, %1, %2;" : "=r"(hb) : "f"(v.w), "f"(v.z));
}

#define EPI_STRIDE 528          // 132 floats, 16B-aligned transpose stride

// fp16 GEMM smem: double-buffered A (2 x 16KB) + B (2 x 8KB)
#define F_A(c) ((uint32_t)(c) * 16384u)
#define F_B(c) (32768u + (uint32_t)(c) * 8192u)
#define SMEM_F16 49408

// =============================================================
// Kernel 0: fused prep. grid (B). hbias + emb->xf16 + hidden->xf16.
// =============================================================
__global__ void __launch_bounds__(256) prep_kernel(
    const float* __restrict__ hidden, const float* __restrict__ We,
    const float* __restrict__ be_p, const float* __restrict__ emb,
    const int* __restrict__ x_tok)
{
    const int b = blockIdx.x, t = threadIdx.x;
    const int lane = t & 31, wid = t >> 5;
    __shared__ float red[8];
    {
        float4 hv = ((const float4*)hidden)[b * 256 + t];
        float4 wv = ((const float4*)We)[512 + t];
        float p = hv.x * wv.x + hv.y * wv.y + hv.z * wv.z + hv.w * wv.w;
#pragma unroll
        for (int o = 16; o > 0; o >>= 1) p += __shfl_xor_sync(0xffffffffu, p, o);
        if (lane == 0) red[wid] = p;
    }
    __syncthreads();
    if (t == 0) {
        float s = be_p[0];
#pragma unroll
        for (int w = 0; w < 8; w++) s += red[w];
        g_hbias[b] = s;
    }
    const int tok = x_tok[b];
    for (int j = t; j < Ev; j += 256)
        g_xf16[b * XK + D2H + j] = __float2half_rn(emb[(size_t)tok * Ev + j]);
    for (int j = t; j < Hv; j += 256)
        g_xf16[b * XK + D2H + Ev + j] = __float2half_rn(hidden[b * Hv + j]);
}

// =============================================================
// Kernel 1: attention. grid (SPLITS=8, B), 256 thr, 128 rows/CTA.
// 4-row tiles, register double-buffered loads, 1 sync/tile.
// Unnormalized softmax (relu energy >= 0, bounded; exp safe).
// =============================================================
__device__ __forceinline__ void attn_load(float4 ev[8], const float4* tbase, int t) {
#pragma unroll
    for (int r = 0; r < 4; r++) {
        ev[2 * r]     = tbase[r * 512 + t];
        ev[2 * r + 1] = tbase[r * 512 + 256 + t];
    }
}
__global__ void __launch_bounds__(256) attn_kernel(
    const float* __restrict__ enc, const float* __restrict__ We)
{
    const int b = blockIdx.y, sp = blockIdx.x, t = threadIdx.x;
    const int lane = t & 31, wid = t >> 5;
    __shared__ float red[2][8][4];

    const float4* We4 = (const float4*)We;
    const float4 w0 = We4[t];
    const float4 w1 = We4[256 + t];
    const float hb = g_hbias[b];

    float acc[8] = {0.f, 0.f, 0.f, 0.f, 0.f, 0.f, 0.f, 0.f};
    float lsum = 0.f;
    const float4* encb = (const float4*)enc + ((size_t)(b * Sv + sp * 128)) * 512;

    float4 evA[8], evB[8];
    attn_load(evA, encb, t);

#define ATTN_PROC(BUF, TILE_EXPR)                                              \
    {                                                                          \
        const int tile = (TILE_EXPR);                                          \
        const int par = tile & 1;                                              \
        float d[4];                                                            \
        _Pragma("unroll")                                                      \
        for (int r = 0; r < 4; r++) {                                          \
            d[r] = BUF[2*r].x * w0.x + BUF[2*r].y * w0.y                       \
                 + BUF[2*r].z * w0.z + BUF[2*r].w * w0.w                       \
                 + BUF[2*r+1].x * w1.x + BUF[2*r+1].y * w1.y                   \
                 + BUF[2*r+1].z * w1.z + BUF[2*r+1].w * w1.w;                  \
            _Pragma("unroll")                                                  \
            for (int o = 16; o > 0; o >>= 1)                                   \
                d[r] += __shfl_xor_sync(0xffffffffu, d[r], o);                 \
        }                                                                      \
        if (lane == 0) {                                                       \
            _Pragma("unroll")                                                  \
            for (int r = 0; r < 4; r++) red[par][wid][r] = d[r];               \
        }                                                                      \
        __syncthreads();                                                       \
        _Pragma("unroll")                                                      \
        for (int r = 0; r < 4; r++) {                                          \
            float s = hb;                                                      \
            _Pragma("unroll")                                                  \
            for (int w2 = 0; w2 < 8; w2++) s += red[par][w2][r];               \
            s = fmaxf(s, 0.f);                                                 \
            float wgt = __expf(s);                                             \
            lsum += wgt;                                                       \
            acc[0] += wgt * BUF[2*r].x;   acc[1] += wgt * BUF[2*r].y;          \
            acc[2] += wgt * BUF[2*r].z;   acc[3] += wgt * BUF[2*r].w;          \
            acc[4] += wgt * BUF[2*r+1].x; acc[5] += wgt * BUF[2*r+1].y;        \
            acc[6] += wgt * BUF[2*r+1].z; acc[7] += wgt * BUF[2*r+1].w;        \
        }                                                                      \
    }

    for (int tp = 0; tp < 16; tp++) {
        attn_load(evB, encb + (size_t)(2 * tp + 1) * 4 * 512, t);
        ATTN_PROC(evA, 2 * tp);
        if (tp < 15)
            attn_load(evA, encb + (size_t)(2 * tp + 2) * 4 * 512, t);
        ATTN_PROC(evB, 2 * tp + 1);
    }
#undef ATTN_PROC

    float4* pacc = (float4*)(g_partial_acc + ((size_t)(b * SPLITS + sp)) * D2H);
    pacc[t]       = make_float4(acc[0], acc[1], acc[2], acc[3]);
    pacc[256 + t] = make_float4(acc[4], acc[5], acc[6], acc[7]);
    if (t == 0) g_partial_l[b * SPLITS + sp] = lsum;
}

// =============================================================
// Kernel 2: combine partials -> c_i (fp16 head of x_full). grid (8, B).
// =============================================================
__global__ void __launch_bounds__(256) combine_kernel()
{
    const int q = blockIdx.x, b = blockIdx.y, t = threadIdx.x;
    float s = 0.f;
#pragma unroll
    for (int i = 0; i < SPLITS; i++) s += g_partial_l[b * SPLITS + i];
    const float inv = 1.f / s;
    const int c = q * 256 + t;
    float a = 0.f;
#pragma unroll
    for (int i = 0; i < SPLITS; i++)
        a += g_partial_acc[((size_t)(b * SPLITS + i)) * D2H + c];
    g_xf16[b * XK + c] = __float2half_rn(a * inv);
}

// ============= fp16 fragment loaders (lds32 path, proven) ===============
__device__ __forceinline__ void frag_a(uint32_t tile, int w, int g, int tg,
                                       int ks, uint32_t a[4]) {
    uint32_t r0 = (uint32_t)(16 * w + g);
    uint32_t k0 = (uint32_t)((16 * ks + 2 * tg) * 2);
    a[0] = lds32(tile + sw128(r0 * 128 + k0));
    a[1] = lds32(tile + sw128((r0 + 8) * 128 + k0));
    a[2] = lds32(tile + sw128(r0 * 128 + k0 + 16));
    a[3] = lds32(tile + sw128((r0 + 8) * 128 + k0 + 16));
}
__device__ __forceinline__ void frag_b(uint32_t tile, int j, int g, int tg,
                                       int ks, uint32_t bfr[2]) {
    uint32_t n = (uint32_t)(8 * j + g);
    uint32_t k0 = (uint32_t)((16 * ks + 2 * tg) * 2);
    bfr[0] = lds32(tile + sw128(n * 128 + k0));
    bfr[1] = lds32(tile + sw128(n * 128 + k0 + 16));
}

// =============================================================
// Kernel 3: gates GEMM v2 — single-pass fp16 (vocab-v6 recipe).
// grid (32 gate-tiles, 4 K-splits), 256 thr. K=896/split (14 chunks).
// A (W) LDG->cvt->STS double-buffered; B (g_xf16) cp.async ring.
// 32 HMMA/warp/chunk. One sync per chunk.
// =============================================================
__global__ void __launch_bounds__(256) gates_mma(
    const float* __restrict__ W_ih, const float* __restrict__ W_hh)
{
    extern __shared__ char dsm[];
    const uint32_t sb = (smem_u32(dsm) + 127u) & ~127u;
    const int t = threadIdx.x, w = t >> 5, lane = t & 31;
    const int g = lane >> 2, tg = lane & 3;
    const int gbase = blockIdx.x * 128;
    const int k0base = blockIdx.y * 896;

    float acc[8][4] = {};
    float4 aP[8];

    // A chunk 0 -> regs
    {
        const int kg = k0base;
        const bool ih = (kg < 2560);
#pragma unroll
        for (int i = 0; i < 8; i++) {
            int e = i * 256 + t, row = e >> 4, c4 = e & 15;
            int og = gbase + row;
            aP[i] = ih ? *(const float4*)(W_ih + (size_t)og * 2560 + kg + c4 * 4)
                       : *(const float4*)(W_hh + (size_t)og * 1024 + (kg - 2560) + c4 * 4);
        }
    }
    // B chunk 0 -> cp.async (fp16 x_full)
#pragma unroll
    for (int i = 0; i < 2; i++) {
        int e = i * 256 + t, n = e >> 3, sg = e & 7;
        uint32_t off = sw128((uint32_t)(n * 128 + sg * 16));
        cp16(sb + F_B(0) + off, g_xf16 + (size_t)n * XK + k0base + sg * 8);
    }
    CP_COMMIT;
    // convert A chunk 0 -> A buf 0
#pragma unroll
    for (int i = 0; i < 8; i++) {
        int e = i * 256 + t, row = e >> 4, c4 = e & 15;
        uint32_t ha, hb2; cvt_h4(aP[i], ha, hb2);
        sts_v2(sb + F_A(0) + sw128((uint32_t)(row * 128 + c4 * 8)), ha, hb2);
    }
    CP_WAIT(0);
    __syncthreads();

    for (int ch = 0; ch < 14; ch++) {
        const uint32_t cur = (uint32_t)(ch & 1);
        const uint32_t nxt = cur ^ 1u;
        const uint32_t aT = sb + F_A(cur);
        const uint32_t bT = sb + F_B(cur);
        const bool more = (ch + 1 < 14);

        if (more) {
            const int kg = k0base + (ch + 1) * 64;
            const bool ih = (kg < 2560);
#pragma unroll
            for (int i = 0; i < 8; i++) {
                int e = i * 256 + t, row = e >> 4, c4 = e & 15;
                int og = gbase + row;
                aP[i] = ih ? *(const float4*)(W_ih + (size_t)og * 2560 + kg + c4 * 4)
                           : *(const float4*)(W_hh + (size_t)og * 1024 + (kg - 2560) + c4 * 4);
            }
#pragma unroll
            for (int i = 0; i < 2; i++) {
                int e = i * 256 + t, n = e >> 3, sg = e & 7;
                uint32_t off = sw128((uint32_t)(n * 128 + sg * 16));
                cp16(sb + F_B(nxt) + off, g_xf16 + (size_t)n * XK + kg + sg * 8);
            }
            CP_COMMIT;
        }

        // MMA: 4 ks x 8 j = 32 fp16 HMMA
#pragma unroll
        for (int ks = 0; ks < 4; ks++) {
            uint32_t a[4];
            frag_a(aT, w, g, tg, ks, a);
#pragma unroll
            for (int j = 0; j < 8; j++) {
                uint32_t b2[2];
                frag_b(bT, j, g, tg, ks, b2);
                fmma(acc[j], a[0], a[1], a[2], a[3], b2[0], b2[1]);
            }
        }

        if (more) {
#pragma unroll
            for (int i = 0; i < 8; i++) {
                int e = i * 256 + t, row = e >> 4, c4 = e & 15;
                uint32_t ha, hb2; cvt_h4(aP[i], ha, hb2);
                sts_v2(sb + F_A(nxt) + sw128((uint32_t)(row * 128 + c4 * 8)), ha, hb2);
            }
        }
        CP_WAIT(0);
        __syncthreads();
    }

    // epilogue: transpose through smem -> coalesced float4 STG (fp32 partials)
#pragma unroll
    for (int j = 0; j < 8; j++) {
#pragma unroll
        for (int k = 0; k < 4; k++) {
            int bb = 8 * j + 2 * tg + (k & 1);
            int vl = 16 * w + g + ((k >> 1) ? 8 : 0);
            sts32f(sb + (uint32_t)(bb * EPI_STRIDE + vl * 4), acc[j][k]);
        }
    }
    __syncthreads();
    float* gp = g_gparts + (size_t)blockIdx.y * (Bv * G4H);
#pragma unroll
    for (int i = 0; i < 8; i++) {
        int e = i * 256 + t, bb = e >> 5, c4 = e & 31;
        float4 v = lds128f(sb + (uint32_t)(bb * EPI_STRIDE + c4 * 16));
        *(float4*)(gp + (size_t)bb * G4H + gbase + c4 * 4) = v;
    }
}

// =============================================================
// Kernel 4: split-K sum + biases + LSTM pointwise; emits fp16 h.
// grid (4, B).
// =============================================================
__global__ void __launch_bounds__(256) lstm_kernel(
    const float* __restrict__ cell, const float* __restrict__ b_ih,
    const float* __restrict__ b_hh, float* __restrict__ out)
{
    const int b = blockIdx.y, h = blockIdx.x * 256 + threadIdx.x;
    float* h_out = out + (size_t)Bv * Vv;
    float* c_out = h_out + Bv * Hv;
    const int base = b * G4H;
    float gi = 0.f, gf = 0.f, gg = 0.f, go = 0.f;
#pragma unroll
    for (int ksv = 0; ksv < 4; ksv++) {
        const float* gp = g_gparts + (size_t)ksv * (Bv * G4H);
        gi += gp[base + h];
        gf += gp[base + 1024 + h];
        gg += gp[base + 2048 + h];
        go += gp[base + 3072 + h];
    }
    gi += b_ih[h]        + b_hh[h];
    gf += b_ih[1024 + h] + b_hh[1024 + h];
    gg += b_ih[2048 + h] + b_hh[2048 + h];
    go += b_ih[3072 + h] + b_hh[3072 + h];
    float si = 1.f / (1.f + expf(-gi));
    float sf = 1.f / (1.f + expf(-gf));
    float so = 1.f / (1.f + expf(-go));
    float c  = sf * cell[b * Hv + h] + si * tanhf(gg);
    float hn = so * tanhf(c);
    c_out[b * Hv + h] = c;
    h_out[b * Hv + h] = hn;
    g_hf16[b * Hv + h] = __float2half_rn(hn);
}

// =============================================================
// Kernel 5: vocab GEMM (fp16 + ldmatrix, unchanged from best).
// grid (393), 256 thr.
// =============================================================
__global__ void __launch_bounds__(256) vocab_mma(
    const float* __restrict__ Wf, const float* __restrict__ bf,
    float* __restrict__ pred)
{
    extern __shared__ char dsm[];
    const uint32_t sb = (smem_u32(dsm) + 127u) & ~127u;
    const int t = threadIdx.x, w = t >> 5, lane = t & 31;
    const int g = lane >> 2, tg = lane & 3;
    const int vbase = blockIdx.x * 128;

    const int seg = lane >> 3, rsel = lane & 7;
    const uint32_t kx   = (uint32_t)((seg >> 1) * 16);
    const uint32_t xorv = (uint32_t)(rsel << 4);
    const uint32_t arow = (uint32_t)(16 * w + (seg & 1) * 8 + rsel);
    const uint32_t abase = arow * 128;
    const uint32_t nb0   = (uint32_t)(((seg & 1) * 8 + rsel) * 128);

    float acc[8][4] = {};
    float4 aP[8];

#pragma unroll
    for (int i = 0; i < 8; i++) {
        int e = i * 256 + t, row = e >> 4, c4 = e & 15;
        int vg = vbase + row;
        aP[i] = (vg < Vv) ? *(const float4*)(Wf + (size_t)vg * Hv + c4 * 4)
                          : make_float4(0.f, 0.f, 0.f, 0.f);
    }
#pragma unroll
    for (int i = 0; i < 2; i++) {
        int e = i * 256 + t, n = e >> 3, sg = e & 7;
        uint32_t off = sw128((uint32_t)(n * 128 + sg * 16));
        cp16(sb + F_B(0) + off, g_hf16 + (size_t)n * Hv + sg * 8);
    }
    CP_COMMIT;
#pragma unroll
    for (int i = 0; i < 8; i++) {
        int e = i * 256 + t, row = e >> 4, c4 = e & 15;
        uint32_t ha, hb2; cvt_h4(aP[i], ha, hb2);
        sts_v2(sb + F_A(0) + sw128((uint32_t)(row * 128 + c4 * 8)), ha, hb2);
    }
    CP_WAIT(0);
    __syncthreads();

    for (int ch = 0; ch < 16; ch++) {
        const uint32_t cur = (uint32_t)(ch & 1);
        const uint32_t nxt = cur ^ 1u;
        const uint32_t aT = sb + F_A(cur);
        const uint32_t bT = sb + F_B(cur);
        const bool more = (ch + 1 < 16);

        if (more) {
            const int kb = (ch + 1) * 64;
#pragma unroll
            for (int i = 0; i < 8; i++) {
                int e = i * 256 + t, row = e >> 4, c4 = e & 15;
                int vg = vbase + row;
                aP[i] = (vg < Vv)
                      ? *(const float4*)(Wf + (size_t)vg * Hv + kb + c4 * 4)
                      : make_float4(0.f, 0.f, 0.f, 0.f);
            }
#pragma unroll
            for (int i = 0; i < 2; i++) {
                int e = i * 256 + t, n = e >> 3, sg = e & 7;
                uint32_t off = sw128((uint32_t)(n * 128 + sg * 16));
                cp16(sb + F_B(nxt) + off, g_hf16 + (size_t)n * Hv + kb + sg * 8);
            }
            CP_COMMIT;
        }

#pragma unroll
        for (int ks = 0; ks < 4; ks++) {
            const uint32_t kb2 = ((uint32_t)(ks * 32) + kx) ^ xorv;
            uint32_t a0, a1, a2, a3;
            LDSM_X4(a0, a1, a2, a3, aT + abase + kb2);
#pragma unroll
            for (int u = 0; u < 4; u++) {
                uint32_t m0, m1, m2, m3;
                LDSM_X4(m0, m1, m2, m3, bT + (uint32_t)(u * 2048) + nb0 + kb2);
                fmma(acc[2 * u],     a0, a1, a2, a3, m0, m2);
                fmma(acc[2 * u + 1], a0, a1, a2, a3, m1, m3);
            }
        }

        if (more) {
#pragma unroll
            for (int i = 0; i < 8; i++) {
                int e = i * 256 + t, row = e >> 4, c4 = e & 15;
                uint32_t ha, hb2; cvt_h4(aP[i], ha, hb2);
                sts_v2(sb + F_A(nxt) + sw128((uint32_t)(row * 128 + c4 * 8)), ha, hb2);
            }
        }
        CP_WAIT(0);
        __syncthreads();
    }

    // epilogue: transpose via smem, add bias, scalar STG
#pragma unroll
    for (int j = 0; j < 8; j++) {
#pragma unroll
        for (int k = 0; k < 4; k++) {
            int bb = 8 * j + 2 * tg + (k & 1);
            int vl = 16 * w + g + ((k >> 1) ? 8 : 0);
            sts32f(sb + (uint32_t)(bb * EPI_STRIDE + vl * 4), acc[j][k]);
        }
    }
    __syncthreads();
#pragma unroll
    for (int i = 0; i < 8; i++) {
        int e = i * 256 + t, bb = e >> 5, c4 = e & 31;
        float4 v = lds128f(sb + (uint32_t)(bb * EPI_STRIDE + c4 * 16));
        int vg = vbase + c4 * 4;
        float* prow = pred + (size_t)bb * Vv;
        float vv[4] = {v.x, v.y, v.z, v.w};
#pragma unroll
        for (int d = 0; d < 4; d++)
            if (vg + d < Vv) prow[vg + d] = vv[d] + bf[vg + d];
    }
}

// =============================================================
extern "C" void kernel_launch(void* const* d_in, const int* in_sizes, int n_in,
                              void* d_out, int out_size)
{
    const float* enc    = (const float*)d_in[0];
    const int*   x_tok  = (const int*)  d_in[1];
    const float* hidden = (const float*)d_in[2];
    const float* cell   = (const float*)d_in[3];
    const float* emb    = (const float*)d_in[4];
    const float* We     = (const float*)d_in[5];
    const float* be     = (const float*)d_in[6];
    const float* W_ih   = (const float*)d_in[7];
    const float* W_hh   = (const float*)d_in[8];
    const float* b_ih   = (const float*)d_in[9];
    const float* b_hh   = (const float*)d_in[10];
    const float* Wf     = (const float*)d_in[11];
    const float* bf     = (const float*)d_in[12];

    float* out   = (float*)d_out;
    float* pred  = out;                          // [B, V]

    cudaFuncSetAttribute(gates_mma, cudaFuncAttributeMaxDynamicSharedMemorySize, SMEM_F16);
    cudaFuncSetAttribute(vocab_mma, cudaFuncAttributeMaxDynamicSharedMemorySize, SMEM_F16);

    prep_kernel   <<<Bv, 256>>>(hidden, We, be, emb, x_tok);
    attn_kernel   <<<dim3(SPLITS, Bv), 256>>>(enc, We);
    combine_kernel<<<dim3(8, Bv), 256>>>();
    gates_mma     <<<dim3(32, 4), 256, SMEM_F16>>>(W_ih, W_hh);
    lstm_kernel   <<<dim3(4, Bv), 256>>>(cell, b_ih, b_hh, out);
    vocab_mma     <<<(Vv + 127) / 128, 256, SMEM_F16>>>(Wf, bf, pred);
}

// round 14
// speedup vs baseline: 1.3024x; 1.0181x over previous
#include <cuda_runtime.h>
#include <cuda_bf16.h>
#include <cuda_fp16.h>
#include <cstdint>
#include <math.h>

#define Bv   64
#define Sv   1024
#define Hv   1024
#define Ev   512
#define Vv   50257
#define D2H  2048
#define XK   3584   // 2H + E + H
#define G4H  4096
#define SPLITS 8
#define GSPLIT 8    // gates split-K

// ---------------- scratch (device globals; no runtime allocation) ----------
__device__ float g_hbias[Bv];
__device__ float g_partial_l[Bv * SPLITS];
__device__ float g_partial_acc[(size_t)Bv * SPLITS * D2H];   // 4 MB
__device__ __half g_xf16[Bv * XK];                            // x_full fp16
__device__ float g_gparts[GSPLIT * (size_t)Bv * G4H];         // 8 MB
__device__ __half g_hf16[Bv * Hv];                            // h_next fp16

// =================== helpers (base PTX only, no sm_103a features) ==========
__device__ __forceinline__ uint32_t smem_u32(const void* p) {
    uint32_t a;
    asm("{ .reg .u64 tmp; cvta.to.shared.u64 tmp, %1; cvt.u32.u64 %0, tmp; }"
        : "=r"(a) : "l"(p));
    return a;
}
__device__ __forceinline__ uint32_t lds32(uint32_t addr) {
    uint32_t v;
    asm volatile("ld.shared.b32 %0, [%1];" : "=r"(v) : "r"(addr));
    return v;
}
__device__ __forceinline__ void sts_v2(uint32_t addr, uint32_t a, uint32_t b) {
    asm volatile("st.shared.v2.b32 [%0], {%1, %2};" :: "r"(addr), "r"(a), "r"(b));
}
__device__ __forceinline__ void sts32f(uint32_t addr, float v) {
    asm volatile("st.shared.f32 [%0], %1;" :: "r"(addr), "f"(v));
}
__device__ __forceinline__ float4 lds128f(uint32_t addr) {
    float4 v;
    asm volatile("ld.shared.v4.f32 {%0,%1,%2,%3}, [%4];"
        : "=f"(v.x), "=f"(v.y), "=f"(v.z), "=f"(v.w) : "r"(addr));
    return v;
}
__device__ __forceinline__ void cp16(uint32_t dst, const void* src) {
    asm volatile("cp.async.cg.shared.global [%0], [%1], 16;"
        :: "r"(dst), "l"(src) : "memory");
}
#define CP_COMMIT  asm volatile("cp.async.commit_group;" ::: "memory")
#define CP_WAIT(n) asm volatile("cp.async.wait_group %0;" :: "n"(n) : "memory")
#define LDSM_X4(r0, r1, r2, r3, addr) \
    asm volatile("ldmatrix.sync.aligned.m8n8.x4.shared.b16 {%0,%1,%2,%3}, [%4];" \
        : "=r"(r0), "=r"(r1), "=r"(r2), "=r"(r3) : "r"(addr))

__device__ __forceinline__ uint32_t sw128(uint32_t off) {
    return off ^ ((off >> 3) & 0x70);
}
// m16n8k16 fp16 MMA, f32 accum (base PTX, sm_80+)
__device__ __forceinline__ void fmma(float* c, uint32_t a0, uint32_t a1,
                                     uint32_t a2, uint32_t a3,
                                     uint32_t b0, uint32_t b1) {
    asm volatile(
        "mma.sync.aligned.m16n8k16.row.col.f32.f16.f16.f32 "
        "{%0,%1,%2,%3}, {%4,%5,%6,%7}, {%8,%9}, {%0,%1,%2,%3};"
        : "+f"(c[0]), "+f"(c[1]), "+f"(c[2]), "+f"(c[3])
        : "r"(a0), "r"(a1), "r"(a2), "r"(a3), "r"(b0), "r"(b1));
}
// fp32x4 -> fp16x2 pair
__device__ __forceinline__ void cvt_h4(float4 v, uint32_t& ha, uint32_t& hb) {
    asm("cvt.rn.f16x2.f32 %0, %1, %2;" : "=r"(ha) : "f"(v.y), "f"(v.x));
    asm("cvt.rn.f16x2.f32 %0, %1, %2;" : "=r"(hb) : "f"(v.w), "f"(v.z));
}

#define EPI_STRIDE 528          // 132 floats, 16B-aligned transpose stride

// fp16 GEMM smem: double-buffered A (2 x 16KB) + B (2 x 8KB)
#define F_A(c) ((uint32_t)(c) * 16384u)
#define F_B(c) (32768u + (uint32_t)(c) * 8192u)
#define SMEM_F16 49408

// =============================================================
// Kernel 0: fused prep. grid (B). hbias + emb->xf16 + hidden->xf16.
// =============================================================
__global__ void __launch_bounds__(256) prep_kernel(
    const float* __restrict__ hidden, const float* __restrict__ We,
    const float* __restrict__ be_p, const float* __restrict__ emb,
    const int* __restrict__ x_tok)
{
    const int b = blockIdx.x, t = threadIdx.x;
    const int lane = t & 31, wid = t >> 5;
    __shared__ float red[8];
    {
        float4 hv = ((const float4*)hidden)[b * 256 + t];
        float4 wv = ((const float4*)We)[512 + t];
        float p = hv.x * wv.x + hv.y * wv.y + hv.z * wv.z + hv.w * wv.w;
#pragma unroll
        for (int o = 16; o > 0; o >>= 1) p += __shfl_xor_sync(0xffffffffu, p, o);
        if (lane == 0) red[wid] = p;
    }
    __syncthreads();
    if (t == 0) {
        float s = be_p[0];
#pragma unroll
        for (int w = 0; w < 8; w++) s += red[w];
        g_hbias[b] = s;
    }
    const int tok = x_tok[b];
    for (int j = t; j < Ev; j += 256)
        g_xf16[b * XK + D2H + j] = __float2half_rn(emb[(size_t)tok * Ev + j]);
    for (int j = t; j < Hv; j += 256)
        g_xf16[b * XK + D2H + Ev + j] = __float2half_rn(hidden[b * Hv + j]);
}

// =============================================================
// Kernel 1: attention. grid (SPLITS=8, B), 256 thr, 128 rows/CTA.
// 4-row tiles, register double-buffered loads, 1 sync/tile.
// Unnormalized softmax (relu energy >= 0, bounded; exp safe).
// =============================================================
__device__ __forceinline__ void attn_load(float4 ev[8], const float4* tbase, int t) {
#pragma unroll
    for (int r = 0; r < 4; r++) {
        ev[2 * r]     = tbase[r * 512 + t];
        ev[2 * r + 1] = tbase[r * 512 + 256 + t];
    }
}
__global__ void __launch_bounds__(256) attn_kernel(
    const float* __restrict__ enc, const float* __restrict__ We)
{
    const int b = blockIdx.y, sp = blockIdx.x, t = threadIdx.x;
    const int lane = t & 31, wid = t >> 5;
    __shared__ float red[2][8][4];

    const float4* We4 = (const float4*)We;
    const float4 w0 = We4[t];
    const float4 w1 = We4[256 + t];
    const float hb = g_hbias[b];

    float acc[8] = {0.f, 0.f, 0.f, 0.f, 0.f, 0.f, 0.f, 0.f};
    float lsum = 0.f;
    const float4* encb = (const float4*)enc + ((size_t)(b * Sv + sp * 128)) * 512;

    float4 evA[8], evB[8];
    attn_load(evA, encb, t);

#define ATTN_PROC(BUF, TILE_EXPR)                                              \
    {                                                                          \
        const int tile = (TILE_EXPR);                                          \
        const int par = tile & 1;                                              \
        float d[4];                                                            \
        _Pragma("unroll")                                                      \
        for (int r = 0; r < 4; r++) {                                          \
            d[r] = BUF[2*r].x * w0.x + BUF[2*r].y * w0.y                       \
                 + BUF[2*r].z * w0.z + BUF[2*r].w * w0.w                       \
                 + BUF[2*r+1].x * w1.x + BUF[2*r+1].y * w1.y                   \
                 + BUF[2*r+1].z * w1.z + BUF[2*r+1].w * w1.w;                  \
            _Pragma("unroll")                                                  \
            for (int o = 16; o > 0; o >>= 1)                                   \
                d[r] += __shfl_xor_sync(0xffffffffu, d[r], o);                 \
        }                                                                      \
        if (lane == 0) {                                                       \
            _Pragma("unroll")                                                  \
            for (int r = 0; r < 4; r++) red[par][wid][r] = d[r];               \
        }                                                                      \
        __syncthreads();                                                       \
        _Pragma("unroll")                                                      \
        for (int r = 0; r < 4; r++) {                                          \
            float s = hb;                                                      \
            _Pragma("unroll")                                                  \
            for (int w2 = 0; w2 < 8; w2++) s += red[par][w2][r];               \
            s = fmaxf(s, 0.f);                                                 \
            float wgt = __expf(s);                                             \
            lsum += wgt;                                                       \
            acc[0] += wgt * BUF[2*r].x;   acc[1] += wgt * BUF[2*r].y;          \
            acc[2] += wgt * BUF[2*r].z;   acc[3] += wgt * BUF[2*r].w;          \
            acc[4] += wgt * BUF[2*r+1].x; acc[5] += wgt * BUF[2*r+1].y;        \
            acc[6] += wgt * BUF[2*r+1].z; acc[7] += wgt * BUF[2*r+1].w;        \
        }                                                                      \
    }

    for (int tp = 0; tp < 16; tp++) {
        attn_load(evB, encb + (size_t)(2 * tp + 1) * 4 * 512, t);
        ATTN_PROC(evA, 2 * tp);
        if (tp < 15)
            attn_load(evA, encb + (size_t)(2 * tp + 2) * 4 * 512, t);
        ATTN_PROC(evB, 2 * tp + 1);
    }
#undef ATTN_PROC

    float4* pacc = (float4*)(g_partial_acc + ((size_t)(b * SPLITS + sp)) * D2H);
    pacc[t]       = make_float4(acc[0], acc[1], acc[2], acc[3]);
    pacc[256 + t] = make_float4(acc[4], acc[5], acc[6], acc[7]);
    if (t == 0) g_partial_l[b * SPLITS + sp] = lsum;
}

// =============================================================
// Kernel 2: combine partials -> c_i (fp16 head of x_full). grid (8, B).
// =============================================================
__global__ void __launch_bounds__(256) combine_kernel()
{
    const int q = blockIdx.x, b = blockIdx.y, t = threadIdx.x;
    float s = 0.f;
#pragma unroll
    for (int i = 0; i < SPLITS; i++) s += g_partial_l[b * SPLITS + i];
    const float inv = 1.f / s;
    const int c = q * 256 + t;
    float a = 0.f;
#pragma unroll
    for (int i = 0; i < SPLITS; i++)
        a += g_partial_acc[((size_t)(b * SPLITS + i)) * D2H + c];
    g_xf16[b * XK + c] = __float2half_rn(a * inv);
}

// ============= fp16 fragment loaders (lds32 path, proven) ===============
__device__ __forceinline__ void frag_a(uint32_t tile, int w, int g, int tg,
                                       int ks, uint32_t a[4]) {
    uint32_t r0 = (uint32_t)(16 * w + g);
    uint32_t k0 = (uint32_t)((16 * ks + 2 * tg) * 2);
    a[0] = lds32(tile + sw128(r0 * 128 + k0));
    a[1] = lds32(tile + sw128((r0 + 8) * 128 + k0));
    a[2] = lds32(tile + sw128(r0 * 128 + k0 + 16));
    a[3] = lds32(tile + sw128((r0 + 8) * 128 + k0 + 16));
}
__device__ __forceinline__ void frag_b(uint32_t tile, int j, int g, int tg,
                                       int ks, uint32_t bfr[2]) {
    uint32_t n = (uint32_t)(8 * j + g);
    uint32_t k0 = (uint32_t)((16 * ks + 2 * tg) * 2);
    bfr[0] = lds32(tile + sw128(n * 128 + k0));
    bfr[1] = lds32(tile + sw128(n * 128 + k0 + 16));
}

// =============================================================
// Kernel 3: gates GEMM v3 — single-pass fp16, split-K=8.
// grid (32 gate-tiles, 8 K-splits), 256 thr. K=448/split (7 chunks).
// A (W) LDG->cvt->STS double-buffered; B (g_xf16) cp.async ring.
// =============================================================
__global__ void __launch_bounds__(256) gates_mma(
    const float* __restrict__ W_ih, const float* __restrict__ W_hh)
{
    extern __shared__ char dsm[];
    const uint32_t sb = (smem_u32(dsm) + 127u) & ~127u;
    const int t = threadIdx.x, w = t >> 5, lane = t & 31;
    const int g = lane >> 2, tg = lane & 3;
    const int gbase = blockIdx.x * 128;
    const int k0base = blockIdx.y * 448;

    float acc[8][4] = {};
    float4 aP[8];

    // A chunk 0 -> regs
    {
        const int kg = k0base;
        const bool ih = (kg < 2560);
#pragma unroll
        for (int i = 0; i < 8; i++) {
            int e = i * 256 + t, row = e >> 4, c4 = e & 15;
            int og = gbase + row;
            aP[i] = ih ? *(const float4*)(W_ih + (size_t)og * 2560 + kg + c4 * 4)
                       : *(const float4*)(W_hh + (size_t)og * 1024 + (kg - 2560) + c4 * 4);
        }
    }
    // B chunk 0 -> cp.async (fp16 x_full)
#pragma unroll
    for (int i = 0; i < 2; i++) {
        int e = i * 256 + t, n = e >> 3, sg = e & 7;
        uint32_t off = sw128((uint32_t)(n * 128 + sg * 16));
        cp16(sb + F_B(0) + off, g_xf16 + (size_t)n * XK + k0base + sg * 8);
    }
    CP_COMMIT;
    // convert A chunk 0 -> A buf 0
#pragma unroll
    for (int i = 0; i < 8; i++) {
        int e = i * 256 + t, row = e >> 4, c4 = e & 15;
        uint32_t ha, hb2; cvt_h4(aP[i], ha, hb2);
        sts_v2(sb + F_A(0) + sw128((uint32_t)(row * 128 + c4 * 8)), ha, hb2);
    }
    CP_WAIT(0);
    __syncthreads();

    for (int ch = 0; ch < 7; ch++) {
        const uint32_t cur = (uint32_t)(ch & 1);
        const uint32_t nxt = cur ^ 1u;
        const uint32_t aT = sb + F_A(cur);
        const uint32_t bT = sb + F_B(cur);
        const bool more = (ch + 1 < 7);

        if (more) {
            const int kg = k0base + (ch + 1) * 64;
            const bool ih = (kg < 2560);
#pragma unroll
            for (int i = 0; i < 8; i++) {
                int e = i * 256 + t, row = e >> 4, c4 = e & 15;
                int og = gbase + row;
                aP[i] = ih ? *(const float4*)(W_ih + (size_t)og * 2560 + kg + c4 * 4)
                           : *(const float4*)(W_hh + (size_t)og * 1024 + (kg - 2560) + c4 * 4);
            }
#pragma unroll
            for (int i = 0; i < 2; i++) {
                int e = i * 256 + t, n = e >> 3, sg = e & 7;
                uint32_t off = sw128((uint32_t)(n * 128 + sg * 16));
                cp16(sb + F_B(nxt) + off, g_xf16 + (size_t)n * XK + kg + sg * 8);
            }
            CP_COMMIT;
        }

        // MMA: 4 ks x 8 j = 32 fp16 HMMA
#pragma unroll
        for (int ks = 0; ks < 4; ks++) {
            uint32_t a[4];
            frag_a(aT, w, g, tg, ks, a);
#pragma unroll
            for (int j = 0; j < 8; j++) {
                uint32_t b2[2];
                frag_b(bT, j, g, tg, ks, b2);
                fmma(acc[j], a[0], a[1], a[2], a[3], b2[0], b2[1]);
            }
        }

        if (more) {
#pragma unroll
            for (int i = 0; i < 8; i++) {
                int e = i * 256 + t, row = e >> 4, c4 = e & 15;
                uint32_t ha, hb2; cvt_h4(aP[i], ha, hb2);
                sts_v2(sb + F_A(nxt) + sw128((uint32_t)(row * 128 + c4 * 8)), ha, hb2);
            }
        }
        CP_WAIT(0);
        __syncthreads();
    }

    // epilogue: transpose through smem -> coalesced float4 STG (fp32 partials)
#pragma unroll
    for (int j = 0; j < 8; j++) {
#pragma unroll
        for (int k = 0; k < 4; k++) {
            int bb = 8 * j + 2 * tg + (k & 1);
            int vl = 16 * w + g + ((k >> 1) ? 8 : 0);
            sts32f(sb + (uint32_t)(bb * EPI_STRIDE + vl * 4), acc[j][k]);
        }
    }
    __syncthreads();
    float* gp = g_gparts + (size_t)blockIdx.y * (Bv * G4H);
#pragma unroll
    for (int i = 0; i < 8; i++) {
        int e = i * 256 + t, bb = e >> 5, c4 = e & 31;
        float4 v = lds128f(sb + (uint32_t)(bb * EPI_STRIDE + c4 * 16));
        *(float4*)(gp + (size_t)bb * G4H + gbase + c4 * 4) = v;
    }
}

// =============================================================
// Kernel 4: split-K sum (8 slices) + biases + LSTM pointwise;
// emits fp16 h. grid (4, B).
// =============================================================
__global__ void __launch_bounds__(256) lstm_kernel(
    const float* __restrict__ cell, const float* __restrict__ b_ih,
    const float* __restrict__ b_hh, float* __restrict__ out)
{
    const int b = blockIdx.y, h = blockIdx.x * 256 + threadIdx.x;
    float* h_out = out + (size_t)Bv * Vv;
    float* c_out = h_out + Bv * Hv;
    const int base = b * G4H;
    float gi = 0.f, gf = 0.f, gg = 0.f, go = 0.f;
#pragma unroll
    for (int ksv = 0; ksv < GSPLIT; ksv++) {
        const float* gp = g_gparts + (size_t)ksv * (Bv * G4H);
        gi += gp[base + h];
        gf += gp[base + 1024 + h];
        gg += gp[base + 2048 + h];
        go += gp[base + 3072 + h];
    }
    gi += b_ih[h]        + b_hh[h];
    gf += b_ih[1024 + h] + b_hh[1024 + h];
    gg += b_ih[2048 + h] + b_hh[2048 + h];
    go += b_ih[3072 + h] + b_hh[3072 + h];
    float si = 1.f / (1.f + expf(-gi));
    float sf = 1.f / (1.f + expf(-gf));
    float so = 1.f / (1.f + expf(-go));
    float c  = sf * cell[b * Hv + h] + si * tanhf(gg);
    float hn = so * tanhf(c);
    c_out[b * Hv + h] = c;
    h_out[b * Hv + h] = hn;
    g_hf16[b * Hv + h] = __float2half_rn(hn);
}

// =============================================================
// Kernel 5: vocab GEMM (fp16 + ldmatrix, unchanged from best).
// grid (393), 256 thr.
// =============================================================
__global__ void __launch_bounds__(256) vocab_mma(
    const float* __restrict__ Wf, const float* __restrict__ bf,
    float* __restrict__ pred)
{
    extern __shared__ char dsm[];
    const uint32_t sb = (smem_u32(dsm) + 127u) & ~127u;
    const int t = threadIdx.x, w = t >> 5, lane = t & 31;
    const int g = lane >> 2, tg = lane & 3;
    const int vbase = blockIdx.x * 128;

    const int seg = lane >> 3, rsel = lane & 7;
    const uint32_t kx   = (uint32_t)((seg >> 1) * 16);
    const uint32_t xorv = (uint32_t)(rsel << 4);
    const uint32_t arow = (uint32_t)(16 * w + (seg & 1) * 8 + rsel);
    const uint32_t abase = arow * 128;
    const uint32_t nb0   = (uint32_t)(((seg & 1) * 8 + rsel) * 128);

    float acc[8][4] = {};
    float4 aP[8];

#pragma unroll
    for (int i = 0; i < 8; i++) {
        int e = i * 256 + t, row = e >> 4, c4 = e & 15;
        int vg = vbase + row;
        aP[i] = (vg < Vv) ? *(const float4*)(Wf + (size_t)vg * Hv + c4 * 4)
                          : make_float4(0.f, 0.f, 0.f, 0.f);
    }
#pragma unroll
    for (int i = 0; i < 2; i++) {
        int e = i * 256 + t, n = e >> 3, sg = e & 7;
        uint32_t off = sw128((uint32_t)(n * 128 + sg * 16));
        cp16(sb + F_B(0) + off, g_hf16 + (size_t)n * Hv + sg * 8);
    }
    CP_COMMIT;
#pragma unroll
    for (int i = 0; i < 8; i++) {
        int e = i * 256 + t, row = e >> 4, c4 = e & 15;
        uint32_t ha, hb2; cvt_h4(aP[i], ha, hb2);
        sts_v2(sb + F_A(0) + sw128((uint32_t)(row * 128 + c4 * 8)), ha, hb2);
    }
    CP_WAIT(0);
    __syncthreads();

    for (int ch = 0; ch < 16; ch++) {
        const uint32_t cur = (uint32_t)(ch & 1);
        const uint32_t nxt = cur ^ 1u;
        const uint32_t aT = sb + F_A(cur);
        const uint32_t bT = sb + F_B(cur);
        const bool more = (ch + 1 < 16);

        if (more) {
            const int kb = (ch + 1) * 64;
#pragma unroll
            for (int i = 0; i < 8; i++) {
                int e = i * 256 + t, row = e >> 4, c4 = e & 15;
                int vg = vbase + row;
                aP[i] = (vg < Vv)
                      ? *(const float4*)(Wf + (size_t)vg * Hv + kb + c4 * 4)
                      : make_float4(0.f, 0.f, 0.f, 0.f);
            }
#pragma unroll
            for (int i = 0; i < 2; i++) {
                int e = i * 256 + t, n = e >> 3, sg = e & 7;
                uint32_t off = sw128((uint32_t)(n * 128 + sg * 16));
                cp16(sb + F_B(nxt) + off, g_hf16 + (size_t)n * Hv + kb + sg * 8);
            }
            CP_COMMIT;
        }

#pragma unroll
        for (int ks = 0; ks < 4; ks++) {
            const uint32_t kb2 = ((uint32_t)(ks * 32) + kx) ^ xorv;
            uint32_t a0, a1, a2, a3;
            LDSM_X4(a0, a1, a2, a3, aT + abase + kb2);
#pragma unroll
            for (int u = 0; u < 4; u++) {
                uint32_t m0, m1, m2, m3;
                LDSM_X4(m0, m1, m2, m3, bT + (uint32_t)(u * 2048) + nb0 + kb2);
                fmma(acc[2 * u],     a0, a1, a2, a3, m0, m2);
                fmma(acc[2 * u + 1], a0, a1, a2, a3, m1, m3);
            }
        }

        if (more) {
#pragma unroll
            for (int i = 0; i < 8; i++) {
                int e = i * 256 + t, row = e >> 4, c4 = e & 15;
                uint32_t ha, hb2; cvt_h4(aP[i], ha, hb2);
                sts_v2(sb + F_A(nxt) + sw128((uint32_t)(row * 128 + c4 * 8)), ha, hb2);
            }
        }
        CP_WAIT(0);
        __syncthreads();
    }

    // epilogue: transpose via smem, add bias, scalar STG
#pragma unroll
    for (int j = 0; j < 8; j++) {
#pragma unroll
        for (int k = 0; k < 4; k++) {
            int bb = 8 * j + 2 * tg + (k & 1);
            int vl = 16 * w + g + ((k >> 1) ? 8 : 0);
            sts32f(sb + (uint32_t)(bb * EPI_STRIDE + vl * 4), acc[j][k]);
        }
    }
    __syncthreads();
#pragma unroll
    for (int i = 0; i < 8; i++) {
        int e = i * 256 + t, bb = e >> 5, c4 = e & 31;
        float4 v = lds128f(sb + (uint32_t)(bb * EPI_STRIDE + c4 * 16));
        int vg = vbase + c4 * 4;
        float* prow = pred + (size_t)bb * Vv;
        float vv[4] = {v.x, v.y, v.z, v.w};
#pragma unroll
        for (int d = 0; d < 4; d++)
            if (vg + d < Vv) prow[vg + d] = vv[d] + bf[vg + d];
    }
}

// =============================================================
extern "C" void kernel_launch(void* const* d_in, const int* in_sizes, int n_in,
                              void* d_out, int out_size)
{
    const float* enc    = (const float*)d_in[0];
    const int*   x_tok  = (const int*)  d_in[1];
    const float* hidden = (const float*)d_in[2];
    const float* cell   = (const float*)d_in[3];
    const float* emb    = (const float*)d_in[4];
    const float* We     = (const float*)d_in[5];
    const float* be     = (const float*)d_in[6];
    const float* W_ih   = (const float*)d_in[7];
    const float* W_hh   = (const float*)d_in[8];
    const float* b_ih   = (const float*)d_in[9];
    const float* b_hh   = (const float*)d_in[10];
    const float* Wf     = (const float*)d_in[11];
    const float* bf     = (const float*)d_in[12];

    float* out   = (float*)d_out;
    float* pred  = out;                          // [B, V]

    cudaFuncSetAttribute(gates_mma, cudaFuncAttributeMaxDynamicSharedMemorySize, SMEM_F16);
    cudaFuncSetAttribute(vocab_mma, cudaFuncAttributeMaxDynamicSharedMemorySize, SMEM_F16);

    prep_kernel   <<<Bv, 256>>>(hidden, We, be, emb, x_tok);
    attn_kernel   <<<dim3(SPLITS, Bv), 256>>>(enc, We);
    combine_kernel<<<dim3(8, Bv), 256>>>();
    gates_mma     <<<dim3(32, GSPLIT), 256, SMEM_F16>>>(W_ih, W_hh);
    lstm_kernel   <<<dim3(4, Bv), 256>>>(cell, b_ih, b_hh, out);
    vocab_mma     <<<(Vv + 127) / 128, 256, SMEM_F16>>>(Wf, bf, pred);
}